// round 1
// baseline (speedup 1.0000x reference)
#include <cuda_runtime.h>

#define BATCH 1024
#define NV 6890
#define NJ 24
#define NSHAPE 10
#define KPOSE 207
#define PF_STRIDE 208
#define N3 (NV*3)

// main-kernel tiling
#define BT 64     // batches per block
#define VT 32     // vertices per block
#define NT 96     // VT*3 columns
#define KT 8      // K chunk

__constant__ int c_parents[NJ] = {-1,0,0,0,1,2,3,4,5,6,7,8,9,9,9,12,13,14,16,17,18,19,20,21};

// scratch (no allocations allowed)
__device__ float g_JRs[NJ*3*NSHAPE];     // J_regressor @ shapedirs
__device__ float g_Jbase[NJ*3];          // J_regressor @ v_template
__device__ float g_pf[BATCH*PF_STRIDE];  // pose_feature, zero-padded to 208
__device__ float g_Arel[BATCH*NJ*12];    // relative transforms [R|t] 3x4

// ---------------------------------------------------------------------------
// Kernel 1: fold J_regressor into tiny per-joint tensors.
// 792 outputs, each a dot product of length NV.
// ---------------------------------------------------------------------------
__global__ void k_jreg(const float* __restrict__ JR,
                       const float* __restrict__ sd,
                       const float* __restrict__ vt) {
    int o = blockIdx.x;                 // 0..791
    int j = o / 33;
    int rem = o % 33;
    int c = rem / 11;
    int l = rem % 11;
    float s = 0.f;
    for (int v = threadIdx.x; v < NV; v += blockDim.x) {
        float r = JR[j*NV + v];
        float x = (l < NSHAPE) ? sd[v*30 + c*10 + l] : vt[v*3 + c];
        s += r * x;
    }
    __shared__ float red[128];
    red[threadIdx.x] = s;
    __syncthreads();
    for (int st = 64; st > 0; st >>= 1) {
        if (threadIdx.x < st) red[threadIdx.x] += red[threadIdx.x + st];
        __syncthreads();
    }
    if (threadIdx.x == 0) {
        if (l < NSHAPE) g_JRs[(j*3 + c)*NSHAPE + l] = red[0];
        else            g_Jbase[j*3 + c] = red[0];
    }
}

// ---------------------------------------------------------------------------
// Kernel 2: warp per batch. Joints, pose_feature, kinematic chain, A_rel.
// ---------------------------------------------------------------------------
__global__ void k_joints(const float* __restrict__ betas,
                         const float* __restrict__ grot,
                         const float* __restrict__ bpose,
                         float* __restrict__ out_joints) {
    int b = blockIdx.x;
    int lane = threadIdx.x;
    __shared__ float sJt[NJ*3];
    __shared__ float sA[NJ*12];   // A[j] as 3x4 [m*4+n], t at n=3

    // Jt = Jbase + JRs @ betas
    for (int idx = lane; idx < NJ*3; idx += 32) {
        float v = g_Jbase[idx];
        const float* jr = &g_JRs[idx*NSHAPE];
        const float* be = &betas[b*NSHAPE];
        #pragma unroll
        for (int l = 0; l < NSHAPE; l++) v += jr[l]*be[l];
        sJt[idx] = v;
    }
    // pose_feature = body_pose - I, flattened, zero-padded stride
    for (int idx = lane; idx < KPOSE; idx += 32) {
        int rr = (idx % 9) / 3, cc = idx % 3;
        g_pf[b*PF_STRIDE + idx] = bpose[b*KPOSE + idx] - ((rr == cc) ? 1.f : 0.f);
    }
    if (lane == 0) g_pf[b*PF_STRIDE + KPOSE] = 0.f;
    __syncwarp();

    if (lane == 0) {
        // joint 0
        const float* R0 = &grot[b*9];
        #pragma unroll
        for (int m = 0; m < 3; m++) {
            sA[m*4+0] = R0[m*3+0];
            sA[m*4+1] = R0[m*3+1];
            sA[m*4+2] = R0[m*3+2];
            sA[m*4+3] = sJt[m];
        }
        // chain
        for (int j = 1; j < NJ; j++) {
            int p = c_parents[j];
            const float* Rl = &bpose[b*KPOSE + (j-1)*9];
            float tl[3];
            #pragma unroll
            for (int m = 0; m < 3; m++) tl[m] = sJt[j*3+m] - sJt[p*3+m];
            const float* Ap = &sA[p*12];
            float* Aj = &sA[j*12];
            #pragma unroll
            for (int m = 0; m < 3; m++) {
                float r0 = Ap[m*4+0], r1 = Ap[m*4+1], r2 = Ap[m*4+2];
                #pragma unroll
                for (int n = 0; n < 3; n++)
                    Aj[m*4+n] = r0*Rl[0*3+n] + r1*Rl[1*3+n] + r2*Rl[2*3+n];
                Aj[m*4+3] = r0*tl[0] + r1*tl[1] + r2*tl[2] + Ap[m*4+3];
            }
        }
    }
    __syncwarp();

    if (lane < NJ) {
        int j = lane;
        const float* Aj = &sA[j*12];
        float* arel = &g_Arel[(b*NJ + j)*12];
        float jt0 = sJt[j*3+0], jt1 = sJt[j*3+1], jt2 = sJt[j*3+2];
        #pragma unroll
        for (int m = 0; m < 3; m++) {
            float r0 = Aj[m*4+0], r1 = Aj[m*4+1], r2 = Aj[m*4+2];
            float t = Aj[m*4+3];
            out_joints[(b*NJ + j)*3 + m] = t;
            arel[m*4+0] = r0;
            arel[m*4+1] = r1;
            arel[m*4+2] = r2;
            arel[m*4+3] = t - (r0*jt0 + r1*jt1 + r2*jt2);
        }
    }
}

// ---------------------------------------------------------------------------
// Kernel 3: fused shape blend + pose GEMM + LBS.
// Block: 64 batches x 32 vertices, 256 threads, micro-tile 4b x 2v x 3c.
// ---------------------------------------------------------------------------
__global__ __launch_bounds__(256, 2)
void k_main(const float* __restrict__ betas,
            const float* __restrict__ vt,
            const float* __restrict__ sd,
            const float* __restrict__ pd,
            const float* __restrict__ w,
            float* __restrict__ out_v) {
    __shared__ float sA[KT][BT];       // pose_feature chunk, k-major
    __shared__ float sB[KT][NT];       // posedirs chunk
    __shared__ float sBet[BT][NSHAPE];
    __shared__ float sShape[VT][30];   // [v][c*10+l]
    __shared__ float sVt[VT][3];
    __shared__ float sW[VT][NJ];
    __shared__ float sAj[BT][12];      // A_rel for current joint

    int tid = threadIdx.x;
    int tn = tid & 15;                 // vertex group: vertices 2*tn, 2*tn+1
    int tm = tid >> 4;                 // batch group: batches 4*tm .. 4*tm+3
    int b0 = blockIdx.y * BT;
    int v0 = blockIdx.x * VT;
    int n0 = v0 * 3;

    for (int i = tid; i < BT*NSHAPE; i += 256) {
        int bb = i / NSHAPE, l = i % NSHAPE;
        sBet[bb][l] = betas[(b0+bb)*NSHAPE + l];
    }
    for (int i = tid; i < VT*30; i += 256) {
        int vv = i / 30, r = i % 30;
        sShape[vv][r] = (v0+vv < NV) ? sd[(v0+vv)*30 + r] : 0.f;
    }
    for (int i = tid; i < VT*3; i += 256) {
        int vv = i / 3, c = i % 3;
        sVt[vv][c] = (v0+vv < NV) ? vt[(v0+vv)*3 + c] : 0.f;
    }
    for (int i = tid; i < VT*NJ; i += 256) {
        int vv = i / NJ, jj = i % NJ;
        sW[vv][jj] = (v0+vv < NV) ? w[(v0+vv)*NJ + jj] : 0.f;
    }
    __syncthreads();

    // v_posed accumulators, init with v_template + shape blend
    float p[4][2][3];
    #pragma unroll
    for (int bi = 0; bi < 4; bi++) {
        int brow = 4*tm + bi;
        #pragma unroll
        for (int vi = 0; vi < 2; vi++) {
            int vloc = 2*tn + vi;
            #pragma unroll
            for (int c = 0; c < 3; c++) {
                float acc = sVt[vloc][c];
                #pragma unroll
                for (int l = 0; l < NSHAPE; l++)
                    acc += sBet[brow][l] * sShape[vloc][c*10 + l];
                p[bi][vi][c] = acc;
            }
        }
    }

    // pose GEMM: p += pose_feature @ posedirs  (K padded to 208 with zeros)
    for (int k0 = 0; k0 < PF_STRIDE; k0 += KT) {
        __syncthreads();
        {
            int i = tid;
            int bb = i >> 3, kk = i & 7;
            sA[kk][bb] = g_pf[(b0+bb)*PF_STRIDE + k0 + kk];
            i = tid + 256;
            bb = i >> 3; kk = i & 7;
            sA[kk][bb] = g_pf[(b0+bb)*PF_STRIDE + k0 + kk];
        }
        #pragma unroll
        for (int t = 0; t < 3; t++) {
            int i = tid + 256*t;
            int kk = i / NT, col = i % NT;
            int kg = k0 + kk, cg = n0 + col;
            sB[kk][col] = (kg < KPOSE && cg < N3) ? pd[(size_t)kg*N3 + cg] : 0.f;
        }
        __syncthreads();
        #pragma unroll
        for (int kk = 0; kk < KT; kk++) {
            float4 a = *(const float4*)&sA[kk][4*tm];
            float2 b01 = *(const float2*)&sB[kk][6*tn + 0];
            float2 b23 = *(const float2*)&sB[kk][6*tn + 2];
            float2 b45 = *(const float2*)&sB[kk][6*tn + 4];
            float am[4] = {a.x, a.y, a.z, a.w};
            float bv[6] = {b01.x, b01.y, b23.x, b23.y, b45.x, b45.y};
            #pragma unroll
            for (int bi = 0; bi < 4; bi++)
                #pragma unroll
                for (int vi = 0; vi < 2; vi++)
                    #pragma unroll
                    for (int c = 0; c < 3; c++)
                        p[bi][vi][c] += am[bi] * bv[vi*3 + c];
        }
    }

    // LBS: out = sum_j w[v,j] * (A_rel[b,j] @ [p;1])
    float o[4][2][3];
    #pragma unroll
    for (int bi = 0; bi < 4; bi++)
        #pragma unroll
        for (int vi = 0; vi < 2; vi++)
            #pragma unroll
            for (int c = 0; c < 3; c++)
                o[bi][vi][c] = 0.f;

    for (int j = 0; j < NJ; j++) {
        __syncthreads();
        #pragma unroll
        for (int t = 0; t < 3; t++) {
            int i = tid + 256*t;
            int bb = i / 12, r = i % 12;
            sAj[bb][r] = g_Arel[((size_t)(b0+bb)*NJ + j)*12 + r];
        }
        __syncthreads();
        #pragma unroll
        for (int bi = 0; bi < 4; bi++) {
            int brow = 4*tm + bi;
            float4 A0 = *(const float4*)&sAj[brow][0];
            float4 A1 = *(const float4*)&sAj[brow][4];
            float4 A2 = *(const float4*)&sAj[brow][8];
            #pragma unroll
            for (int vi = 0; vi < 2; vi++) {
                float wv = sW[2*tn + vi][j];
                float px = p[bi][vi][0], py = p[bi][vi][1], pz = p[bi][vi][2];
                float d0 = A0.w + A0.x*px + A0.y*py + A0.z*pz;
                float d1 = A1.w + A1.x*px + A1.y*py + A1.z*pz;
                float d2 = A2.w + A2.x*px + A2.y*py + A2.z*pz;
                o[bi][vi][0] += wv*d0;
                o[bi][vi][1] += wv*d1;
                o[bi][vi][2] += wv*d2;
            }
        }
    }

    // store
    #pragma unroll
    for (int bi = 0; bi < 4; bi++) {
        #pragma unroll
        for (int vi = 0; vi < 2; vi++) {
            int vg = v0 + 2*tn + vi;
            if (vg < NV) {
                size_t base = ((size_t)(b0 + 4*tm + bi)*NV + vg)*3;
                out_v[base+0] = o[bi][vi][0];
                out_v[base+1] = o[bi][vi][1];
                out_v[base+2] = o[bi][vi][2];
            }
        }
    }
}

// ---------------------------------------------------------------------------
extern "C" void kernel_launch(void* const* d_in, const int* in_sizes, int n_in,
                              void* d_out, int out_size) {
    const float* betas = (const float*)d_in[0];
    const float* grot  = (const float*)d_in[1];
    const float* bpose = (const float*)d_in[2];
    const float* vt    = (const float*)d_in[3];
    const float* sd    = (const float*)d_in[4];
    const float* pd    = (const float*)d_in[5];
    const float* JR    = (const float*)d_in[6];
    const float* w     = (const float*)d_in[7];
    float* out = (float*)d_out;
    float* out_vertices = out;
    float* out_joints = out + (size_t)BATCH*NV*3;

    k_jreg<<<NJ*3*11, 128>>>(JR, sd, vt);
    k_joints<<<BATCH, 32>>>(betas, grot, bpose, out_joints);
    dim3 grid((NV + VT - 1)/VT, BATCH/BT);
    k_main<<<grid, 256>>>(betas, vt, sd, pd, w, out_vertices);
}

// round 2
// speedup vs baseline: 1.1119x; 1.1119x over previous
#include <cuda_runtime.h>
#include <cstdint>

#define BATCH 1024
#define NV 6890
#define NJ 24
#define NSHAPE 10
#define KPOSE 207
#define PF_STRIDE 208
#define N3 (NV*3)

// main-kernel tiling
#define BT 64     // batches per block (M tile)
#define VT 32     // vertices per block
#define NT 96     // VT*3 columns (N tile)
#define KSTEPS 26 // 208 / 8

__constant__ int c_parents[NJ] = {-1,0,0,0,1,2,3,4,5,6,7,8,9,9,9,12,13,14,16,17,18,19,20,21};

// scratch (no allocations allowed) -- zero-initialized device globals
__device__ float g_JRs[NJ*3*NSHAPE];       // J_regressor @ shapedirs
__device__ float g_Jbase[NJ*3];            // J_regressor @ v_template
__device__ float g_pf_hi[BATCH*PF_STRIDE]; // pose_feature hi (tf32), zero-padded
__device__ float g_pf_lo[BATCH*PF_STRIDE]; // pose_feature lo (tf32)
__device__ float g_Arel[BATCH*NJ*12];      // relative transforms [R|t] 3x4
__device__ float g_pd_hi[PF_STRIDE*N3];    // posedirs hi (tf32), row 207 stays 0
__device__ float g_pd_lo[PF_STRIDE*N3];    // posedirs lo (tf32)

__device__ __forceinline__ float tf32_rna(float x) {
    unsigned u;
    asm("cvt.rna.tf32.f32 %0, %1;" : "=r"(u) : "f"(x));
    return __uint_as_float(u);
}

// ---------------------------------------------------------------------------
// Kernel 0: split posedirs into tf32 hi/lo parts.
// ---------------------------------------------------------------------------
__global__ void k_split_pd(const float* __restrict__ pd) {
    long i = (long)blockIdx.x * 256 + threadIdx.x;
    if (i < (long)KPOSE * N3) {
        float x = pd[i];
        float hi = tf32_rna(x);
        g_pd_hi[i] = hi;
        g_pd_lo[i] = tf32_rna(x - hi);
    }
}

// ---------------------------------------------------------------------------
// Kernel 1: fold J_regressor into tiny per-joint tensors.
// One block per (j, c); each thread keeps 11 partial dots.
// ---------------------------------------------------------------------------
__global__ void k_jreg(const float* __restrict__ JR,
                       const float* __restrict__ sd,
                       const float* __restrict__ vt) {
    int j = blockIdx.x / 3;
    int c = blockIdx.x % 3;
    int tid = threadIdx.x;
    float acc[11];
    #pragma unroll
    for (int l = 0; l < 11; l++) acc[l] = 0.f;
    for (int v = tid; v < NV; v += 256) {
        float r = JR[j*NV + v];
        const float* s = &sd[v*30 + c*10];
        #pragma unroll
        for (int l = 0; l < 10; l++) acc[l] += r * s[l];
        acc[10] += r * vt[v*3 + c];
    }
    __shared__ float red[256][12];
    #pragma unroll
    for (int l = 0; l < 11; l++) red[tid][l] = acc[l];
    __syncthreads();
    for (int st = 128; st > 0; st >>= 1) {
        if (tid < st) {
            #pragma unroll
            for (int l = 0; l < 11; l++) red[tid][l] += red[tid + st][l];
        }
        __syncthreads();
    }
    if (tid < 10) g_JRs[(j*3 + c)*NSHAPE + tid] = red[0][tid];
    if (tid == 10) g_Jbase[j*3 + c] = red[0][10];
}

// ---------------------------------------------------------------------------
// Kernel 2: warp per batch. Joints, split pose_feature, chain, A_rel.
// ---------------------------------------------------------------------------
__global__ void k_joints(const float* __restrict__ betas,
                         const float* __restrict__ grot,
                         const float* __restrict__ bpose,
                         float* __restrict__ out_joints) {
    int b = blockIdx.x;
    int lane = threadIdx.x;
    __shared__ float sJt[NJ*3];
    __shared__ float sA[NJ*12];   // A[j] as 3x4 [m*4+n]

    for (int idx = lane; idx < NJ*3; idx += 32) {
        float v = g_Jbase[idx];
        const float* jr = &g_JRs[idx*NSHAPE];
        const float* be = &betas[b*NSHAPE];
        #pragma unroll
        for (int l = 0; l < NSHAPE; l++) v += jr[l]*be[l];
        sJt[idx] = v;
    }
    for (int idx = lane; idx < KPOSE; idx += 32) {
        int rr = (idx % 9) / 3, cc = idx % 3;
        float pf = bpose[b*KPOSE + idx] - ((rr == cc) ? 1.f : 0.f);
        float hi = tf32_rna(pf);
        g_pf_hi[b*PF_STRIDE + idx] = hi;
        g_pf_lo[b*PF_STRIDE + idx] = tf32_rna(pf - hi);
    }
    if (lane == 0) {
        g_pf_hi[b*PF_STRIDE + KPOSE] = 0.f;
        g_pf_lo[b*PF_STRIDE + KPOSE] = 0.f;
    }
    __syncwarp();

    if (lane == 0) {
        const float* R0 = &grot[b*9];
        #pragma unroll
        for (int m = 0; m < 3; m++) {
            sA[m*4+0] = R0[m*3+0];
            sA[m*4+1] = R0[m*3+1];
            sA[m*4+2] = R0[m*3+2];
            sA[m*4+3] = sJt[m];
        }
        for (int j = 1; j < NJ; j++) {
            int p = c_parents[j];
            const float* Rl = &bpose[b*KPOSE + (j-1)*9];
            float tl[3];
            #pragma unroll
            for (int m = 0; m < 3; m++) tl[m] = sJt[j*3+m] - sJt[p*3+m];
            const float* Ap = &sA[p*12];
            float* Aj = &sA[j*12];
            #pragma unroll
            for (int m = 0; m < 3; m++) {
                float r0 = Ap[m*4+0], r1 = Ap[m*4+1], r2 = Ap[m*4+2];
                #pragma unroll
                for (int n = 0; n < 3; n++)
                    Aj[m*4+n] = r0*Rl[0*3+n] + r1*Rl[1*3+n] + r2*Rl[2*3+n];
                Aj[m*4+3] = r0*tl[0] + r1*tl[1] + r2*tl[2] + Ap[m*4+3];
            }
        }
    }
    __syncwarp();

    if (lane < NJ) {
        int j = lane;
        const float* Aj = &sA[j*12];
        float* arel = &g_Arel[(b*NJ + j)*12];
        float jt0 = sJt[j*3+0], jt1 = sJt[j*3+1], jt2 = sJt[j*3+2];
        #pragma unroll
        for (int m = 0; m < 3; m++) {
            float r0 = Aj[m*4+0], r1 = Aj[m*4+1], r2 = Aj[m*4+2];
            float t = Aj[m*4+3];
            out_joints[(b*NJ + j)*3 + m] = t;
            arel[m*4+0] = r0;
            arel[m*4+1] = r1;
            arel[m*4+2] = r2;
            arel[m*4+3] = t - (r0*jt0 + r1*jt1 + r2*jt2);
        }
    }
}

// ---------------------------------------------------------------------------
// Kernel 3: tensor-core pose GEMM (split tf32, 3-pass) + shape blend + LBS.
// Block: 64 batches x 32 vertices (96 cols), 256 threads / 8 warps.
// Warp (wm, wn): rows 16*wm..16*wm+15, cols 48*wn..48*wn+47 (6 n8-frags).
// ---------------------------------------------------------------------------
#define ASTRIDE 72
#define BSTRIDE 104
#define PSTRIDE 100

union SmemU {
    struct {
        float Ah[8][ASTRIDE];
        float Al[8][ASTRIDE];
        float Bh[8][BSTRIDE];
        float Bl[8][BSTRIDE];
    } g;
    float P[BT][PSTRIDE];
};

#define MMA_TF32(D, A0,A1,A2,A3, B0,B1) \
    asm volatile("mma.sync.aligned.m16n8k8.row.col.f32.tf32.tf32.f32 " \
                 "{%0,%1,%2,%3},{%4,%5,%6,%7},{%8,%9},{%0,%1,%2,%3};" \
                 : "+f"(D[0]), "+f"(D[1]), "+f"(D[2]), "+f"(D[3]) \
                 : "r"(A0), "r"(A1), "r"(A2), "r"(A3), "r"(B0), "r"(B1))

__global__ __launch_bounds__(256, 2)
void k_main(const float* __restrict__ betas,
            const float* __restrict__ vt,
            const float* __restrict__ sd,
            const float* __restrict__ w,
            float* __restrict__ out_v) {
    __shared__ SmemU u;
    __shared__ float sBet[BT][NSHAPE];
    __shared__ float sShape[VT][30];
    __shared__ float sVt[VT][3];
    __shared__ float sW[VT][NJ];
    __shared__ float sAj[BT][12];

    int tid = threadIdx.x;
    int lane = tid & 31;
    int wid = tid >> 5;
    int wm = wid & 3;          // m-block (rows 16*wm .. +15)
    int wn = wid >> 2;         // n-half  (cols 48*wn .. +47)
    int g4 = lane >> 2;        // groupID
    int t4 = lane & 3;         // threadID in group
    int b0 = blockIdx.y * BT;
    int v0 = blockIdx.x * VT;
    int n0 = v0 * 3;

    // small per-block data (persistent smem region)
    for (int i = tid; i < BT*NSHAPE; i += 256) {
        int bb = i / NSHAPE, l = i % NSHAPE;
        sBet[bb][l] = betas[(b0+bb)*NSHAPE + l];
    }
    for (int i = tid; i < VT*30; i += 256) {
        int vv = i / 30, r = i % 30;
        sShape[vv][r] = (v0+vv < NV) ? sd[(v0+vv)*30 + r] : 0.f;
    }
    for (int i = tid; i < VT*3; i += 256) {
        int vv = i / 3, c = i % 3;
        sVt[vv][c] = (v0+vv < NV) ? vt[(v0+vv)*3 + c] : 0.f;
    }
    for (int i = tid; i < VT*NJ; i += 256) {
        int vv = i / NJ, jj = i % NJ;
        sW[vv][jj] = (v0+vv < NV) ? w[(v0+vv)*NJ + jj] : 0.f;
    }

    // accumulators: 6 fragments of 16x8
    float d[6][4];
    #pragma unroll
    for (int f = 0; f < 6; f++)
        #pragma unroll
        for (int q = 0; q < 4; q++) d[f][q] = 0.f;

    // prefetch registers
    float pa_h[2], pa_l[2], pb_h[3], pb_l[3];
    // A load indices: i = tid + 256*t -> row=i>>3, kk=i&7
    int arow0 = tid >> 3, akk0 = tid & 7;
    int arow1 = (tid+256) >> 3, akk1 = tid & 7;
    // B load indices: i = tid + 256*t -> kk=i/96, col=i%96
    int bkk[3], bcol[3];
    #pragma unroll
    for (int t = 0; t < 3; t++) { int i = tid + 256*t; bkk[t] = i / NT; bcol[t] = i % NT; }

    // initial chunk load (k0 = 0)
    {
        const float* ph = &g_pf_hi[(size_t)b0*PF_STRIDE];
        const float* pl = &g_pf_lo[(size_t)b0*PF_STRIDE];
        pa_h[0] = ph[arow0*PF_STRIDE + akk0];
        pa_h[1] = ph[arow1*PF_STRIDE + akk1];
        pa_l[0] = pl[arow0*PF_STRIDE + akk0];
        pa_l[1] = pl[arow1*PF_STRIDE + akk1];
        #pragma unroll
        for (int t = 0; t < 3; t++) {
            int cg = n0 + bcol[t];
            bool ok = (cg < N3);
            size_t off = (size_t)bkk[t]*N3 + cg;
            pb_h[t] = ok ? g_pd_hi[off] : 0.f;
            pb_l[t] = ok ? g_pd_lo[off] : 0.f;
        }
    }

    for (int ks = 0; ks < KSTEPS; ks++) {
        __syncthreads();
        // store prefetched chunk to smem
        u.g.Ah[akk0][arow0] = pa_h[0];
        u.g.Ah[akk1][arow1] = pa_h[1];
        u.g.Al[akk0][arow0] = pa_l[0];
        u.g.Al[akk1][arow1] = pa_l[1];
        #pragma unroll
        for (int t = 0; t < 3; t++) {
            u.g.Bh[bkk[t]][bcol[t]] = pb_h[t];
            u.g.Bl[bkk[t]][bcol[t]] = pb_l[t];
        }
        __syncthreads();

        // issue next chunk loads (latency hidden under mma)
        if (ks + 1 < KSTEPS) {
            int k0n = (ks + 1) * 8;
            const float* ph = &g_pf_hi[(size_t)b0*PF_STRIDE + k0n];
            const float* pl = &g_pf_lo[(size_t)b0*PF_STRIDE + k0n];
            pa_h[0] = ph[arow0*PF_STRIDE + akk0];
            pa_h[1] = ph[arow1*PF_STRIDE + akk1];
            pa_l[0] = pl[arow0*PF_STRIDE + akk0];
            pa_l[1] = pl[arow1*PF_STRIDE + akk1];
            #pragma unroll
            for (int t = 0; t < 3; t++) {
                int cg = n0 + bcol[t];
                bool ok = (cg < N3);
                size_t off = (size_t)(k0n + bkk[t])*N3 + cg;
                pb_h[t] = ok ? g_pd_hi[off] : 0.f;
                pb_l[t] = ok ? g_pd_lo[off] : 0.f;
            }
        }

        // A fragments for this warp's 16 rows
        int ar = 16*wm + g4;
        unsigned ah0 = __float_as_uint(u.g.Ah[t4  ][ar]);
        unsigned ah1 = __float_as_uint(u.g.Ah[t4  ][ar+8]);
        unsigned ah2 = __float_as_uint(u.g.Ah[t4+4][ar]);
        unsigned ah3 = __float_as_uint(u.g.Ah[t4+4][ar+8]);
        unsigned al0 = __float_as_uint(u.g.Al[t4  ][ar]);
        unsigned al1 = __float_as_uint(u.g.Al[t4  ][ar+8]);
        unsigned al2 = __float_as_uint(u.g.Al[t4+4][ar]);
        unsigned al3 = __float_as_uint(u.g.Al[t4+4][ar+8]);

        #pragma unroll
        for (int f = 0; f < 6; f++) {
            int col = 48*wn + 8*f + g4;
            unsigned bh0 = __float_as_uint(u.g.Bh[t4  ][col]);
            unsigned bh1 = __float_as_uint(u.g.Bh[t4+4][col]);
            unsigned bl0 = __float_as_uint(u.g.Bl[t4  ][col]);
            unsigned bl1 = __float_as_uint(u.g.Bl[t4+4][col]);
            MMA_TF32(d[f], ah0, ah1, ah2, ah3, bh0, bh1);
            MMA_TF32(d[f], al0, al1, al2, al3, bh0, bh1);
            MMA_TF32(d[f], ah0, ah1, ah2, ah3, bl0, bl1);
        }
    }

    // spill accumulators to P tile (overwrites A/B smem)
    __syncthreads();
    #pragma unroll
    for (int f = 0; f < 6; f++) {
        int col = 48*wn + 8*f + 2*t4;
        int row = 16*wm + g4;
        u.P[row  ][col  ] = d[f][0];
        u.P[row  ][col+1] = d[f][1];
        u.P[row+8][col  ] = d[f][2];
        u.P[row+8][col+1] = d[f][3];
    }
    __syncthreads();

    // LBS epilogue: thread owns 4 batches x 2 vertices
    int tn = tid & 15;
    int tm = tid >> 4;

    float p[4][2][3];
    #pragma unroll
    for (int bi = 0; bi < 4; bi++) {
        int brow = 4*tm + bi;
        #pragma unroll
        for (int vi = 0; vi < 2; vi++) {
            int vloc = 2*tn + vi;
            #pragma unroll
            for (int c = 0; c < 3; c++) {
                float acc = sVt[vloc][c] + u.P[brow][6*tn + 3*vi + c];
                #pragma unroll
                for (int l = 0; l < NSHAPE; l++)
                    acc += sBet[brow][l] * sShape[vloc][c*10 + l];
                p[bi][vi][c] = acc;
            }
        }
    }

    float o[4][2][3];
    #pragma unroll
    for (int bi = 0; bi < 4; bi++)
        #pragma unroll
        for (int vi = 0; vi < 2; vi++)
            #pragma unroll
            for (int c = 0; c < 3; c++)
                o[bi][vi][c] = 0.f;

    for (int j = 0; j < NJ; j++) {
        __syncthreads();
        #pragma unroll
        for (int t = 0; t < 3; t++) {
            int i = tid + 256*t;
            int bb = i / 12, r = i % 12;
            sAj[bb][r] = g_Arel[((size_t)(b0+bb)*NJ + j)*12 + r];
        }
        __syncthreads();
        #pragma unroll
        for (int bi = 0; bi < 4; bi++) {
            int brow = 4*tm + bi;
            float4 A0 = *(const float4*)&sAj[brow][0];
            float4 A1 = *(const float4*)&sAj[brow][4];
            float4 A2 = *(const float4*)&sAj[brow][8];
            #pragma unroll
            for (int vi = 0; vi < 2; vi++) {
                float wv = sW[2*tn + vi][j];
                float px = p[bi][vi][0], py = p[bi][vi][1], pz = p[bi][vi][2];
                float d0 = A0.w + A0.x*px + A0.y*py + A0.z*pz;
                float d1 = A1.w + A1.x*px + A1.y*py + A1.z*pz;
                float d2 = A2.w + A2.x*px + A2.y*py + A2.z*pz;
                o[bi][vi][0] += wv*d0;
                o[bi][vi][1] += wv*d1;
                o[bi][vi][2] += wv*d2;
            }
        }
    }

    #pragma unroll
    for (int bi = 0; bi < 4; bi++) {
        #pragma unroll
        for (int vi = 0; vi < 2; vi++) {
            int vg = v0 + 2*tn + vi;
            if (vg < NV) {
                size_t base = ((size_t)(b0 + 4*tm + bi)*NV + vg)*3;
                out_v[base+0] = o[bi][vi][0];
                out_v[base+1] = o[bi][vi][1];
                out_v[base+2] = o[bi][vi][2];
            }
        }
    }
}

// ---------------------------------------------------------------------------
extern "C" void kernel_launch(void* const* d_in, const int* in_sizes, int n_in,
                              void* d_out, int out_size) {
    const float* betas = (const float*)d_in[0];
    const float* grot  = (const float*)d_in[1];
    const float* bpose = (const float*)d_in[2];
    const float* vt    = (const float*)d_in[3];
    const float* sd    = (const float*)d_in[4];
    const float* pd    = (const float*)d_in[5];
    const float* JR    = (const float*)d_in[6];
    const float* w     = (const float*)d_in[7];
    float* out = (float*)d_out;
    float* out_vertices = out;
    float* out_joints = out + (size_t)BATCH*NV*3;

    k_split_pd<<<(KPOSE*N3 + 255)/256, 256>>>(pd);
    k_jreg<<<NJ*3, 256>>>(JR, sd, vt);
    k_joints<<<BATCH, 32>>>(betas, grot, bpose, out_joints);
    dim3 grid((NV + VT - 1)/VT, BATCH/BT);
    k_main<<<grid, 256>>>(betas, vt, sd, w, out_vertices);
}

// round 3
// speedup vs baseline: 1.2014x; 1.0805x over previous
#include <cuda_runtime.h>
#include <cstdint>

#define BATCH 1024
#define NV 6890
#define NJ 24
#define NSHAPE 10
#define KPOSE 207
#define PF_STRIDE 208
#define N3 (NV*3)

// main-kernel tiling
#define BT 64     // batches per block (M tile)
#define VT 32     // vertices per block
#define NT 96     // VT*3 columns (N tile)
#define KSTEPS 26 // 208 / 8

#define ASTR 72
#define BSTR 104
#define PSTRIDE 100

__constant__ int c_parents[NJ] = {-1,0,0,0,1,2,3,4,5,6,7,8,9,9,9,12,13,14,16,17,18,19,20,21};

// scratch (no allocations allowed) -- zero-initialized device globals
__device__ float g_JRs[NJ*3*NSHAPE];       // J_regressor @ shapedirs
__device__ float g_Jbase[NJ*3];            // J_regressor @ v_template
__device__ float g_pf_hi[BATCH*PF_STRIDE]; // pose_feature hi (tf32), zero-padded
__device__ float g_pf_lo[BATCH*PF_STRIDE]; // pose_feature lo (tf32)
__device__ float g_Arel[BATCH*NJ*12];      // relative transforms [R|t] 3x4
__device__ float g_pd_hi[PF_STRIDE*N3];    // posedirs tf32 (row 207 stays 0)

__device__ __forceinline__ float tf32_rna(float x) {
    unsigned u;
    asm("cvt.rna.tf32.f32 %0, %1;" : "=r"(u) : "f"(x));
    return __uint_as_float(u);
}

// ---------------------------------------------------------------------------
// Kernel 0: round posedirs to tf32.
// ---------------------------------------------------------------------------
__global__ void k_split_pd(const float* __restrict__ pd) {
    long i = (long)blockIdx.x * 256 + threadIdx.x;
    if (i < (long)KPOSE * N3) {
        g_pd_hi[i] = tf32_rna(pd[i]);
    }
}

// ---------------------------------------------------------------------------
// Kernel 1: fold J_regressor into tiny per-joint tensors.
// ---------------------------------------------------------------------------
__global__ void k_jreg(const float* __restrict__ JR,
                       const float* __restrict__ sd,
                       const float* __restrict__ vt) {
    int j = blockIdx.x / 3;
    int c = blockIdx.x % 3;
    int tid = threadIdx.x;
    float acc[11];
    #pragma unroll
    for (int l = 0; l < 11; l++) acc[l] = 0.f;
    for (int v = tid; v < NV; v += 256) {
        float r = JR[j*NV + v];
        const float* s = &sd[v*30 + c*10];
        #pragma unroll
        for (int l = 0; l < 10; l++) acc[l] += r * s[l];
        acc[10] += r * vt[v*3 + c];
    }
    __shared__ float red[256][12];
    #pragma unroll
    for (int l = 0; l < 11; l++) red[tid][l] = acc[l];
    __syncthreads();
    for (int st = 128; st > 0; st >>= 1) {
        if (tid < st) {
            #pragma unroll
            for (int l = 0; l < 11; l++) red[tid][l] += red[tid + st][l];
        }
        __syncthreads();
    }
    if (tid < 10) g_JRs[(j*3 + c)*NSHAPE + tid] = red[0][tid];
    if (tid == 10) g_Jbase[j*3 + c] = red[0][10];
}

// ---------------------------------------------------------------------------
// Kernel 2: warp per batch. Joints, split pose_feature, chain, A_rel.
// ---------------------------------------------------------------------------
__global__ void k_joints(const float* __restrict__ betas,
                         const float* __restrict__ grot,
                         const float* __restrict__ bpose,
                         float* __restrict__ out_joints) {
    int b = blockIdx.x;
    int lane = threadIdx.x;
    __shared__ float sJt[NJ*3];
    __shared__ float sA[NJ*12];   // A[j] as 3x4 [m*4+n]

    for (int idx = lane; idx < NJ*3; idx += 32) {
        float v = g_Jbase[idx];
        const float* jr = &g_JRs[idx*NSHAPE];
        const float* be = &betas[b*NSHAPE];
        #pragma unroll
        for (int l = 0; l < NSHAPE; l++) v += jr[l]*be[l];
        sJt[idx] = v;
    }
    for (int idx = lane; idx < KPOSE; idx += 32) {
        int rr = (idx % 9) / 3, cc = idx % 3;
        float pf = bpose[b*KPOSE + idx] - ((rr == cc) ? 1.f : 0.f);
        float hi = tf32_rna(pf);
        g_pf_hi[b*PF_STRIDE + idx] = hi;
        g_pf_lo[b*PF_STRIDE + idx] = tf32_rna(pf - hi);
    }
    if (lane == 0) {
        g_pf_hi[b*PF_STRIDE + KPOSE] = 0.f;
        g_pf_lo[b*PF_STRIDE + KPOSE] = 0.f;
    }
    __syncwarp();

    if (lane == 0) {
        const float* R0 = &grot[b*9];
        #pragma unroll
        for (int m = 0; m < 3; m++) {
            sA[m*4+0] = R0[m*3+0];
            sA[m*4+1] = R0[m*3+1];
            sA[m*4+2] = R0[m*3+2];
            sA[m*4+3] = sJt[m];
        }
        for (int j = 1; j < NJ; j++) {
            int p = c_parents[j];
            const float* Rl = &bpose[b*KPOSE + (j-1)*9];
            float tl[3];
            #pragma unroll
            for (int m = 0; m < 3; m++) tl[m] = sJt[j*3+m] - sJt[p*3+m];
            const float* Ap = &sA[p*12];
            float* Aj = &sA[j*12];
            #pragma unroll
            for (int m = 0; m < 3; m++) {
                float r0 = Ap[m*4+0], r1 = Ap[m*4+1], r2 = Ap[m*4+2];
                #pragma unroll
                for (int n = 0; n < 3; n++)
                    Aj[m*4+n] = r0*Rl[0*3+n] + r1*Rl[1*3+n] + r2*Rl[2*3+n];
                Aj[m*4+3] = r0*tl[0] + r1*tl[1] + r2*tl[2] + Ap[m*4+3];
            }
        }
    }
    __syncwarp();

    if (lane < NJ) {
        int j = lane;
        const float* Aj = &sA[j*12];
        float* arel = &g_Arel[(b*NJ + j)*12];
        float jt0 = sJt[j*3+0], jt1 = sJt[j*3+1], jt2 = sJt[j*3+2];
        #pragma unroll
        for (int m = 0; m < 3; m++) {
            float r0 = Aj[m*4+0], r1 = Aj[m*4+1], r2 = Aj[m*4+2];
            float t = Aj[m*4+3];
            out_joints[(b*NJ + j)*3 + m] = t;
            arel[m*4+0] = r0;
            arel[m*4+1] = r1;
            arel[m*4+2] = r2;
            arel[m*4+3] = t - (r0*jt0 + r1*jt1 + r2*jt2);
        }
    }
}

// ---------------------------------------------------------------------------
// Kernel 3: tensor-core pose GEMM (2-pass split tf32 on A, 1x tf32 B),
//           double-buffered smem, + shape blend + LBS with staged A_rel.
// Block: 64 batches x 32 vertices (96 cols), 256 threads / 8 warps.
// ---------------------------------------------------------------------------
union SmemU {
    struct {
        float Ah[2][8][ASTR];
        float Al[2][8][ASTR];
        float Bh[2][8][BSTR];
    } g;
    float P[BT][PSTRIDE];
    float Arel[BT][12][12];    // 12 joints per phase
};

#define MMA_TF32(D, A0,A1,A2,A3, B0,B1) \
    asm volatile("mma.sync.aligned.m16n8k8.row.col.f32.tf32.tf32.f32 " \
                 "{%0,%1,%2,%3},{%4,%5,%6,%7},{%8,%9},{%0,%1,%2,%3};" \
                 : "+f"(D[0]), "+f"(D[1]), "+f"(D[2]), "+f"(D[3]) \
                 : "r"(A0), "r"(A1), "r"(A2), "r"(A3), "r"(B0), "r"(B1))

__global__ __launch_bounds__(256, 2)
void k_main(const float* __restrict__ betas,
            const float* __restrict__ vt,
            const float* __restrict__ sd,
            const float* __restrict__ w,
            float* __restrict__ out_v) {
    __shared__ SmemU u;
    __shared__ float sBet[BT][NSHAPE];
    __shared__ float sShape[VT][30];
    __shared__ float sVt[VT][3];
    __shared__ float sW[VT][NJ];

    int tid = threadIdx.x;
    int lane = tid & 31;
    int wid = tid >> 5;
    int wm = wid & 3;          // rows 16*wm .. +15
    int wn = wid >> 2;         // cols 48*wn .. +47
    int g4 = lane >> 2;
    int t4 = lane & 3;
    int b0 = blockIdx.y * BT;
    int v0 = blockIdx.x * VT;
    int n0 = v0 * 3;

    for (int i = tid; i < BT*NSHAPE; i += 256) {
        int bb = i / NSHAPE, l = i % NSHAPE;
        sBet[bb][l] = betas[(b0+bb)*NSHAPE + l];
    }
    for (int i = tid; i < VT*30; i += 256) {
        int vv = i / 30, r = i % 30;
        sShape[vv][r] = (v0+vv < NV) ? sd[(v0+vv)*30 + r] : 0.f;
    }
    for (int i = tid; i < VT*3; i += 256) {
        int vv = i / 3, c = i % 3;
        sVt[vv][c] = (v0+vv < NV) ? vt[(v0+vv)*3 + c] : 0.f;
    }
    for (int i = tid; i < VT*NJ; i += 256) {
        int vv = i / NJ, jj = i % NJ;
        sW[vv][jj] = (v0+vv < NV) ? w[(v0+vv)*NJ + jj] : 0.f;
    }

    // accumulators: 6 fragments of 16x8
    float d[6][4];
    #pragma unroll
    for (int f = 0; f < 6; f++)
        #pragma unroll
        for (int q = 0; q < 4; q++) d[f][q] = 0.f;

    // load/store index precompute
    int arow0 = tid >> 3, akk0 = tid & 7;
    int arow1 = (tid+256) >> 3, akk1 = tid & 7;
    int bkk[3], bcol[3];
    bool bok[3];
    #pragma unroll
    for (int t = 0; t < 3; t++) {
        int i = tid + 256*t;
        bkk[t] = i / NT; bcol[t] = i % NT;
        bok[t] = (n0 + bcol[t]) < N3;
    }

    float pa_h[2], pa_l[2], pb[3];
    // initial chunk (k0 = 0)
    {
        const float* ph = &g_pf_hi[(size_t)b0*PF_STRIDE];
        const float* pl = &g_pf_lo[(size_t)b0*PF_STRIDE];
        pa_h[0] = ph[arow0*PF_STRIDE + akk0];
        pa_h[1] = ph[arow1*PF_STRIDE + akk1];
        pa_l[0] = pl[arow0*PF_STRIDE + akk0];
        pa_l[1] = pl[arow1*PF_STRIDE + akk1];
        #pragma unroll
        for (int t = 0; t < 3; t++)
            pb[t] = bok[t] ? g_pd_hi[(size_t)bkk[t]*N3 + n0 + bcol[t]] : 0.f;
    }
    __syncthreads();
    // store chunk 0 into stage 0
    u.g.Ah[0][akk0][arow0] = pa_h[0];
    u.g.Ah[0][akk1][arow1] = pa_h[1];
    u.g.Al[0][akk0][arow0] = pa_l[0];
    u.g.Al[0][akk1][arow1] = pa_l[1];
    #pragma unroll
    for (int t = 0; t < 3; t++) u.g.Bh[0][bkk[t]][bcol[t]] = pb[t];
    __syncthreads();

    int ar = 16*wm + g4;
    for (int ks = 0; ks < KSTEPS; ks++) {
        int s = ks & 1;
        bool more = (ks + 1 < KSTEPS);
        if (more) {
            int k0n = (ks + 1) * 8;
            const float* ph = &g_pf_hi[(size_t)b0*PF_STRIDE + k0n];
            const float* pl = &g_pf_lo[(size_t)b0*PF_STRIDE + k0n];
            pa_h[0] = ph[arow0*PF_STRIDE + akk0];
            pa_h[1] = ph[arow1*PF_STRIDE + akk1];
            pa_l[0] = pl[arow0*PF_STRIDE + akk0];
            pa_l[1] = pl[arow1*PF_STRIDE + akk1];
            #pragma unroll
            for (int t = 0; t < 3; t++)
                pb[t] = bok[t] ? g_pd_hi[(size_t)(k0n + bkk[t])*N3 + n0 + bcol[t]] : 0.f;
        }

        // A fragments
        unsigned ah0 = __float_as_uint(u.g.Ah[s][t4  ][ar]);
        unsigned ah1 = __float_as_uint(u.g.Ah[s][t4  ][ar+8]);
        unsigned ah2 = __float_as_uint(u.g.Ah[s][t4+4][ar]);
        unsigned ah3 = __float_as_uint(u.g.Ah[s][t4+4][ar+8]);
        unsigned al0 = __float_as_uint(u.g.Al[s][t4  ][ar]);
        unsigned al1 = __float_as_uint(u.g.Al[s][t4  ][ar+8]);
        unsigned al2 = __float_as_uint(u.g.Al[s][t4+4][ar]);
        unsigned al3 = __float_as_uint(u.g.Al[s][t4+4][ar+8]);

        #pragma unroll
        for (int f = 0; f < 6; f++) {
            int col = 48*wn + 8*f + g4;
            unsigned b0r = __float_as_uint(u.g.Bh[s][t4  ][col]);
            unsigned b1r = __float_as_uint(u.g.Bh[s][t4+4][col]);
            MMA_TF32(d[f], ah0, ah1, ah2, ah3, b0r, b1r);
            MMA_TF32(d[f], al0, al1, al2, al3, b0r, b1r);
        }

        if (more) {
            int sn = s ^ 1;
            u.g.Ah[sn][akk0][arow0] = pa_h[0];
            u.g.Ah[sn][akk1][arow1] = pa_h[1];
            u.g.Al[sn][akk0][arow0] = pa_l[0];
            u.g.Al[sn][akk1][arow1] = pa_l[1];
            #pragma unroll
            for (int t = 0; t < 3; t++) u.g.Bh[sn][bkk[t]][bcol[t]] = pb[t];
        }
        __syncthreads();
    }

    // spill accumulators to P tile (overwrites GEMM buffers)
    #pragma unroll
    for (int f = 0; f < 6; f++) {
        int col = 48*wn + 8*f + 2*t4;
        int row = 16*wm + g4;
        u.P[row  ][col  ] = d[f][0];
        u.P[row  ][col+1] = d[f][1];
        u.P[row+8][col  ] = d[f][2];
        u.P[row+8][col+1] = d[f][3];
    }
    __syncthreads();

    // LBS epilogue: thread owns 4 batches x 2 vertices
    int tn = tid & 15;
    int tm = tid >> 4;

    float p[4][2][3];
    #pragma unroll
    for (int bi = 0; bi < 4; bi++) {
        int brow = 4*tm + bi;
        #pragma unroll
        for (int vi = 0; vi < 2; vi++) {
            int vloc = 2*tn + vi;
            #pragma unroll
            for (int c = 0; c < 3; c++) {
                float acc = sVt[vloc][c] + u.P[brow][6*tn + 3*vi + c];
                #pragma unroll
                for (int l = 0; l < NSHAPE; l++)
                    acc += sBet[brow][l] * sShape[vloc][c*10 + l];
                p[bi][vi][c] = acc;
            }
        }
    }
    __syncthreads();   // all P reads done before Arel staging overwrites union

    float o[4][2][3];
    #pragma unroll
    for (int bi = 0; bi < 4; bi++)
        #pragma unroll
        for (int vi = 0; vi < 2; vi++)
            #pragma unroll
            for (int c = 0; c < 3; c++)
                o[bi][vi][c] = 0.f;

    #pragma unroll
    for (int phase = 0; phase < 2; phase++) {
        // stage A_rel for 12 joints: 64*12*12 = 9216 floats
        #pragma unroll
        for (int t = 0; t < 36; t++) {
            int i = tid + 256*t;
            int bb = i / 144, rem = i % 144;
            int jl = rem / 12, r = rem % 12;
            u.Arel[bb][jl][r] =
                g_Arel[((size_t)(b0+bb)*NJ + phase*12 + jl)*12 + r];
        }
        __syncthreads();

        #pragma unroll
        for (int jl = 0; jl < 12; jl++) {
            int jg = phase*12 + jl;
            #pragma unroll
            for (int bi = 0; bi < 4; bi++) {
                int brow = 4*tm + bi;
                float4 A0 = *(const float4*)&u.Arel[brow][jl][0];
                float4 A1 = *(const float4*)&u.Arel[brow][jl][4];
                float4 A2 = *(const float4*)&u.Arel[brow][jl][8];
                #pragma unroll
                for (int vi = 0; vi < 2; vi++) {
                    float wv = sW[2*tn + vi][jg];
                    float px = p[bi][vi][0], py = p[bi][vi][1], pz = p[bi][vi][2];
                    float d0 = A0.w + A0.x*px + A0.y*py + A0.z*pz;
                    float d1 = A1.w + A1.x*px + A1.y*py + A1.z*pz;
                    float d2 = A2.w + A2.x*px + A2.y*py + A2.z*pz;
                    o[bi][vi][0] += wv*d0;
                    o[bi][vi][1] += wv*d1;
                    o[bi][vi][2] += wv*d2;
                }
            }
        }
        __syncthreads();
    }

    #pragma unroll
    for (int bi = 0; bi < 4; bi++) {
        #pragma unroll
        for (int vi = 0; vi < 2; vi++) {
            int vg = v0 + 2*tn + vi;
            if (vg < NV) {
                size_t base = ((size_t)(b0 + 4*tm + bi)*NV + vg)*3;
                out_v[base+0] = o[bi][vi][0];
                out_v[base+1] = o[bi][vi][1];
                out_v[base+2] = o[bi][vi][2];
            }
        }
    }
}

// ---------------------------------------------------------------------------
extern "C" void kernel_launch(void* const* d_in, const int* in_sizes, int n_in,
                              void* d_out, int out_size) {
    const float* betas = (const float*)d_in[0];
    const float* grot  = (const float*)d_in[1];
    const float* bpose = (const float*)d_in[2];
    const float* vt    = (const float*)d_in[3];
    const float* sd    = (const float*)d_in[4];
    const float* pd    = (const float*)d_in[5];
    const float* JR    = (const float*)d_in[6];
    const float* w     = (const float*)d_in[7];
    float* out = (float*)d_out;
    float* out_vertices = out;
    float* out_joints = out + (size_t)BATCH*NV*3;

    k_split_pd<<<(KPOSE*N3 + 255)/256, 256>>>(pd);
    k_jreg<<<NJ*3, 256>>>(JR, sd, vt);
    k_joints<<<BATCH, 32>>>(betas, grot, bpose, out_joints);
    dim3 grid((NV + VT - 1)/VT, BATCH/BT);
    k_main<<<grid, 256>>>(betas, vt, sd, w, out_vertices);
}

// round 4
// speedup vs baseline: 1.4844x; 1.2355x over previous
#include <cuda_runtime.h>
#include <cstdint>

#define BATCH 1024
#define NV 6890
#define NJ 24
#define NSHAPE 10
#define KPOSE 207
#define N3 (NV*3)          // 20670
#define KA 224             // 207 pf + 10 betas + 2 vt(hi/lo) + 5 zero pad

// big GEMM tiling
#define GM 128
#define GN 128
#define GK 8
#define GKSTEPS (KA/GK)    // 28
#define SSTR 132

// LBS kernel tiling
#define LVT 256            // vertices per block
#define LGB 16             // batches per block
#define WSTR 260
#define TSTR 13

__constant__ int c_parents[NJ] = {-1,0,0,0,1,2,3,4,5,6,7,8,9,9,9,12,13,14,16,17,18,19,20,21};

// scratch (device globals; zero-initialized, pads never written)
__device__ float g_JRs[NJ*3*NSHAPE];
__device__ float g_Jbase[NJ*3];
__device__ float g_Ahi[BATCH*KA];          // [pf | betas | 1 1 | 0...] hi
__device__ float g_Alo[BATCH*KA];          // lo parts (0 for the 1-cols)
__device__ float g_B[KA*N3];               // [posedirs ; shapedirsT ; vt_hi ; vt_lo ; 0] tf32
__device__ float g_Arel[BATCH*NJ*12];      // relative transforms 3x4
__device__ float g_WThi[NJ*NV];            // lbs_weights^T hi
__device__ float g_WTlo[NJ*NV];            // lbs_weights^T lo
__device__ float g_vposed[BATCH*N3];       // 84.7 MB scratch

__device__ __forceinline__ float tf32_rna(float x) {
    unsigned u;
    asm("cvt.rna.tf32.f32 %0, %1;" : "=r"(u) : "f"(x));
    return __uint_as_float(u);
}

#define MMA_TF32(D, A0,A1,A2,A3, B0,B1) \
    asm volatile("mma.sync.aligned.m16n8k8.row.col.f32.tf32.tf32.f32 " \
                 "{%0,%1,%2,%3},{%4,%5,%6,%7},{%8,%9},{%0,%1,%2,%3};" \
                 : "+f"(D[0]), "+f"(D[1]), "+f"(D[2]), "+f"(D[3]) \
                 : "r"(A0), "r"(A1), "r"(A2), "r"(A3), "r"(B0), "r"(B1))

// ---------------------------------------------------------------------------
// Prep: build B matrix (KA x N3) in tf32.
// ---------------------------------------------------------------------------
__global__ void k_prep_B(const float* __restrict__ pd,
                         const float* __restrict__ sd,
                         const float* __restrict__ vt) {
    long i = (long)blockIdx.x * 256 + threadIdx.x;
    long total = (long)(KPOSE + NSHAPE + 2) * N3;   // 219 rows
    if (i >= total) return;
    int row = (int)(i / N3);
    int n = (int)(i % N3);
    float val;
    if (row < KPOSE) {
        val = pd[(size_t)row*N3 + n];
    } else if (row < KPOSE + NSHAPE) {
        int l = row - KPOSE;
        int v = n / 3, c = n % 3;
        val = sd[v*30 + c*10 + l];
    } else if (row == KPOSE + NSHAPE) {
        val = vt[n];
    } else {
        float x = vt[n];
        val = x - tf32_rna(x);
    }
    g_B[(size_t)row*N3 + n] = tf32_rna(val);
}

// ---------------------------------------------------------------------------
// Prep: lbs_weights transposed, split hi/lo.
// ---------------------------------------------------------------------------
__global__ void k_prep_W(const float* __restrict__ w) {
    int i = blockIdx.x * 256 + threadIdx.x;
    if (i >= NJ*NV) return;
    int j = i / NV, v = i % NV;
    float x = w[v*NJ + j];
    float hi = tf32_rna(x);
    g_WThi[i] = hi;
    g_WTlo[i] = tf32_rna(x - hi);
}

// ---------------------------------------------------------------------------
// Fold J_regressor into tiny per-joint tensors.
// ---------------------------------------------------------------------------
__global__ void k_jreg(const float* __restrict__ JR,
                       const float* __restrict__ sd,
                       const float* __restrict__ vt) {
    int j = blockIdx.x / 3;
    int c = blockIdx.x % 3;
    int tid = threadIdx.x;
    float acc[11];
    #pragma unroll
    for (int l = 0; l < 11; l++) acc[l] = 0.f;
    for (int v = tid; v < NV; v += 256) {
        float r = JR[j*NV + v];
        const float* s = &sd[v*30 + c*10];
        #pragma unroll
        for (int l = 0; l < 10; l++) acc[l] += r * s[l];
        acc[10] += r * vt[v*3 + c];
    }
    __shared__ float red[256][12];
    #pragma unroll
    for (int l = 0; l < 11; l++) red[tid][l] = acc[l];
    __syncthreads();
    for (int st = 128; st > 0; st >>= 1) {
        if (tid < st) {
            #pragma unroll
            for (int l = 0; l < 11; l++) red[tid][l] += red[tid + st][l];
        }
        __syncthreads();
    }
    if (tid < 10) g_JRs[(j*3 + c)*NSHAPE + tid] = red[0][tid];
    if (tid == 10) g_Jbase[j*3 + c] = red[0][10];
}

// ---------------------------------------------------------------------------
// Warp per batch: joints, A-matrix (pf+betas+ones split), chain, A_rel.
// ---------------------------------------------------------------------------
__global__ void k_joints(const float* __restrict__ betas,
                         const float* __restrict__ grot,
                         const float* __restrict__ bpose,
                         float* __restrict__ out_joints) {
    int b = blockIdx.x;
    int lane = threadIdx.x;
    __shared__ float sJt[NJ*3];
    __shared__ float sA[NJ*12];

    for (int idx = lane; idx < NJ*3; idx += 32) {
        float v = g_Jbase[idx];
        const float* jr = &g_JRs[idx*NSHAPE];
        const float* be = &betas[b*NSHAPE];
        #pragma unroll
        for (int l = 0; l < NSHAPE; l++) v += jr[l]*be[l];
        sJt[idx] = v;
    }
    // A matrix row: 207 pf + 10 betas + two 1.0 columns
    for (int idx = lane; idx < KPOSE + NSHAPE + 2; idx += 32) {
        float val;
        if (idx < KPOSE) {
            int rr = (idx % 9) / 3, cc = idx % 3;
            val = bpose[b*KPOSE + idx] - ((rr == cc) ? 1.f : 0.f);
        } else if (idx < KPOSE + NSHAPE) {
            val = betas[b*NSHAPE + (idx - KPOSE)];
        } else {
            val = 1.f;
        }
        float hi = tf32_rna(val);
        g_Ahi[b*KA + idx] = hi;
        g_Alo[b*KA + idx] = (idx >= KPOSE + NSHAPE) ? 0.f : tf32_rna(val - hi);
    }
    __syncwarp();

    if (lane == 0) {
        const float* R0 = &grot[b*9];
        #pragma unroll
        for (int m = 0; m < 3; m++) {
            sA[m*4+0] = R0[m*3+0];
            sA[m*4+1] = R0[m*3+1];
            sA[m*4+2] = R0[m*3+2];
            sA[m*4+3] = sJt[m];
        }
        for (int j = 1; j < NJ; j++) {
            int p = c_parents[j];
            const float* Rl = &bpose[b*KPOSE + (j-1)*9];
            float tl[3];
            #pragma unroll
            for (int m = 0; m < 3; m++) tl[m] = sJt[j*3+m] - sJt[p*3+m];
            const float* Ap = &sA[p*12];
            float* Aj = &sA[j*12];
            #pragma unroll
            for (int m = 0; m < 3; m++) {
                float r0 = Ap[m*4+0], r1 = Ap[m*4+1], r2 = Ap[m*4+2];
                #pragma unroll
                for (int n = 0; n < 3; n++)
                    Aj[m*4+n] = r0*Rl[0*3+n] + r1*Rl[1*3+n] + r2*Rl[2*3+n];
                Aj[m*4+3] = r0*tl[0] + r1*tl[1] + r2*tl[2] + Ap[m*4+3];
            }
        }
    }
    __syncwarp();

    if (lane < NJ) {
        int j = lane;
        const float* Aj = &sA[j*12];
        float* arel = &g_Arel[(b*NJ + j)*12];
        float jt0 = sJt[j*3+0], jt1 = sJt[j*3+1], jt2 = sJt[j*3+2];
        #pragma unroll
        for (int m = 0; m < 3; m++) {
            float r0 = Aj[m*4+0], r1 = Aj[m*4+1], r2 = Aj[m*4+2];
            float t = Aj[m*4+3];
            out_joints[(b*NJ + j)*3 + m] = t;
            arel[m*4+0] = r0;
            arel[m*4+1] = r1;
            arel[m*4+2] = r2;
            arel[m*4+3] = t - (r0*jt0 + r1*jt1 + r2*jt2);
        }
    }
}

// ---------------------------------------------------------------------------
// Big GEMM: v_posed(1024 x 20670) = [Ahi+Alo](1024 x 224) @ B(224 x 20670)
// 128x128 block tile, 8 warps (4m x 2n), warp tile 32x64, double-buffered.
// ---------------------------------------------------------------------------
__global__ __launch_bounds__(256, 2)
void k_gemm() {
    __shared__ float sAh[2][GK][SSTR];
    __shared__ float sAl[2][GK][SSTR];
    __shared__ float sB [2][GK][SSTR];

    int tid = threadIdx.x;
    int lane = tid & 31;
    int wid = tid >> 5;
    int wm = wid & 3;          // rows 32*wm .. +31
    int wn = wid >> 2;         // cols 64*wn .. +63
    int g4 = lane >> 2;
    int t4 = lane & 3;
    int n0 = blockIdx.x * GN;
    int m0 = blockIdx.y * GM;

    // load index precompute
    int ak = tid & 7;            // A k within chunk
    int arow0 = tid >> 3;        // + 32*t
    int bk0 = tid >> 7;          // + 2*t
    int bcol = tid & 127;
    bool bok = (n0 + bcol) < N3;

    float d[2][8][4];
    #pragma unroll
    for (int mf = 0; mf < 2; mf++)
        #pragma unroll
        for (int f = 0; f < 8; f++)
            #pragma unroll
            for (int q = 0; q < 4; q++) d[mf][f][q] = 0.f;

    float pah[4], pal[4], pb[4];
    // initial chunk (k0=0)
    #pragma unroll
    for (int t = 0; t < 4; t++) {
        int r = m0 + arow0 + 32*t;
        pah[t] = g_Ahi[r*KA + ak];
        pal[t] = g_Alo[r*KA + ak];
        pb[t] = bok ? g_B[(size_t)(bk0 + 2*t)*N3 + n0 + bcol] : 0.f;
    }
    #pragma unroll
    for (int t = 0; t < 4; t++) {
        sAh[0][ak][arow0 + 32*t] = pah[t];
        sAl[0][ak][arow0 + 32*t] = pal[t];
        sB [0][bk0 + 2*t][bcol] = pb[t];
    }
    __syncthreads();

    int arb = 32*wm + g4;
    for (int ks = 0; ks < GKSTEPS; ks++) {
        int s = ks & 1;
        bool more = (ks + 1 < GKSTEPS);
        if (more) {
            int k0n = (ks + 1) * GK;
            #pragma unroll
            for (int t = 0; t < 4; t++) {
                int r = m0 + arow0 + 32*t;
                pah[t] = g_Ahi[r*KA + k0n + ak];
                pal[t] = g_Alo[r*KA + k0n + ak];
                pb[t] = bok ? g_B[(size_t)(k0n + bk0 + 2*t)*N3 + n0 + bcol] : 0.f;
            }
        }

        unsigned ah[2][4], al[2][4];
        #pragma unroll
        for (int mf = 0; mf < 2; mf++) {
            int ar = arb + 16*mf;
            ah[mf][0] = __float_as_uint(sAh[s][t4  ][ar]);
            ah[mf][1] = __float_as_uint(sAh[s][t4  ][ar+8]);
            ah[mf][2] = __float_as_uint(sAh[s][t4+4][ar]);
            ah[mf][3] = __float_as_uint(sAh[s][t4+4][ar+8]);
            al[mf][0] = __float_as_uint(sAl[s][t4  ][ar]);
            al[mf][1] = __float_as_uint(sAl[s][t4  ][ar+8]);
            al[mf][2] = __float_as_uint(sAl[s][t4+4][ar]);
            al[mf][3] = __float_as_uint(sAl[s][t4+4][ar+8]);
        }
        #pragma unroll
        for (int f = 0; f < 8; f++) {
            int col = 64*wn + 8*f + g4;
            unsigned b0 = __float_as_uint(sB[s][t4  ][col]);
            unsigned b1 = __float_as_uint(sB[s][t4+4][col]);
            #pragma unroll
            for (int mf = 0; mf < 2; mf++) {
                MMA_TF32(d[mf][f], ah[mf][0], ah[mf][1], ah[mf][2], ah[mf][3], b0, b1);
                MMA_TF32(d[mf][f], al[mf][0], al[mf][1], al[mf][2], al[mf][3], b0, b1);
            }
        }

        if (more) {
            int sn = s ^ 1;
            #pragma unroll
            for (int t = 0; t < 4; t++) {
                sAh[sn][ak][arow0 + 32*t] = pah[t];
                sAl[sn][ak][arow0 + 32*t] = pal[t];
                sB [sn][bk0 + 2*t][bcol] = pb[t];
            }
        }
        __syncthreads();
    }

    // direct store (32B-sector aligned pairs)
    #pragma unroll
    for (int mf = 0; mf < 2; mf++) {
        #pragma unroll
        for (int f = 0; f < 8; f++) {
            int row = m0 + 32*wm + 16*mf + g4;
            int cg = n0 + 64*wn + 8*f + 2*t4;
            if (cg < N3) {
                *(float2*)&g_vposed[(size_t)row*N3 + cg] =
                    make_float2(d[mf][f][0], d[mf][f][1]);
                *(float2*)&g_vposed[(size_t)(row+8)*N3 + cg] =
                    make_float2(d[mf][f][2], d[mf][f][3]);
            }
        }
    }
}

// ---------------------------------------------------------------------------
// LBS: per block 256 vertices x 16 batches.
// T(256x12) = W(256x24) @ A_rel_b(24x12) on tensor cores (3-pass split),
// then out = T_R @ v_posed + T_t  (12 MAC per vertex).
// ---------------------------------------------------------------------------
union ULbs {
    float Wst[NJ][WSTR];
    float T[LVT][TSTR];
};

__global__ __launch_bounds__(256, 2)
void k_lbs(float* __restrict__ out_v) {
    __shared__ ULbs u;
    __shared__ float sRh[NJ][16];
    __shared__ float sRl[NJ][16];

    int tid = threadIdx.x;
    int lane = tid & 31;
    int wid = tid >> 5;
    int g4 = lane >> 2;
    int t4 = lane & 3;
    int v0 = blockIdx.x * LVT;
    int b0 = blockIdx.y * LGB;
    int vg = v0 + tid;
    bool vok = vg < NV;

    // stage W hi -> extract fragments -> stage lo -> extract
    unsigned wh[2][3][4], wl[2][3][4];
    #pragma unroll
    for (int k = 0; k < NJ; k++)
        u.Wst[k][tid] = vok ? g_WThi[k*NV + vg] : 0.f;
    __syncthreads();
    #pragma unroll
    for (int mf = 0; mf < 2; mf++) {
        int ar = 32*wid + 16*mf + g4;
        #pragma unroll
        for (int ks = 0; ks < 3; ks++) {
            wh[mf][ks][0] = __float_as_uint(u.Wst[8*ks+t4  ][ar]);
            wh[mf][ks][1] = __float_as_uint(u.Wst[8*ks+t4  ][ar+8]);
            wh[mf][ks][2] = __float_as_uint(u.Wst[8*ks+t4+4][ar]);
            wh[mf][ks][3] = __float_as_uint(u.Wst[8*ks+t4+4][ar+8]);
        }
    }
    __syncthreads();
    #pragma unroll
    for (int k = 0; k < NJ; k++)
        u.Wst[k][tid] = vok ? g_WTlo[k*NV + vg] : 0.f;
    __syncthreads();
    #pragma unroll
    for (int mf = 0; mf < 2; mf++) {
        int ar = 32*wid + 16*mf + g4;
        #pragma unroll
        for (int ks = 0; ks < 3; ks++) {
            wl[mf][ks][0] = __float_as_uint(u.Wst[8*ks+t4  ][ar]);
            wl[mf][ks][1] = __float_as_uint(u.Wst[8*ks+t4  ][ar+8]);
            wl[mf][ks][2] = __float_as_uint(u.Wst[8*ks+t4+4][ar]);
            wl[mf][ks][3] = __float_as_uint(u.Wst[8*ks+t4+4][ar+8]);
        }
    }
    // zero sR pad columns (12..15) once
    if (tid < NJ*4) {
        int j = tid >> 2, c = 12 + (tid & 3);
        sRh[j][c] = 0.f;
        sRl[j][c] = 0.f;
    }

    for (int bi = 0; bi < LGB; bi++) {
        int b = b0 + bi;
        // build A_rel fragments (split)
        {
            int i = tid;
            if (i < NJ*12) {
                int j = i / 12, r = i % 12;
                float x = g_Arel[((size_t)b*NJ + j)*12 + r];
                float hi = tf32_rna(x);
                sRh[j][r] = hi;
                sRl[j][r] = tf32_rna(x - hi);
            }
            i = tid + 256;
            if (i < NJ*12) {
                int j = i / 12, r = i % 12;
                float x = g_Arel[((size_t)b*NJ + j)*12 + r];
                float hi = tf32_rna(x);
                sRh[j][r] = hi;
                sRl[j][r] = tf32_rna(x - hi);
            }
        }
        __syncthreads();   // also orders prev-iter T reads before T overwrite

        float dd[2][2][4];
        #pragma unroll
        for (int mf = 0; mf < 2; mf++)
            #pragma unroll
            for (int nf = 0; nf < 2; nf++)
                #pragma unroll
                for (int q = 0; q < 4; q++) dd[mf][nf][q] = 0.f;

        #pragma unroll
        for (int ks = 0; ks < 3; ks++) {
            #pragma unroll
            for (int nf = 0; nf < 2; nf++) {
                int rc = 8*nf + g4;
                unsigned rh0 = __float_as_uint(sRh[8*ks+t4  ][rc]);
                unsigned rh1 = __float_as_uint(sRh[8*ks+t4+4][rc]);
                unsigned rl0 = __float_as_uint(sRl[8*ks+t4  ][rc]);
                unsigned rl1 = __float_as_uint(sRl[8*ks+t4+4][rc]);
                #pragma unroll
                for (int mf = 0; mf < 2; mf++) {
                    MMA_TF32(dd[mf][nf], wh[mf][ks][0], wh[mf][ks][1], wh[mf][ks][2], wh[mf][ks][3], rh0, rh1);
                    MMA_TF32(dd[mf][nf], wl[mf][ks][0], wl[mf][ks][1], wl[mf][ks][2], wl[mf][ks][3], rh0, rh1);
                    MMA_TF32(dd[mf][nf], wh[mf][ks][0], wh[mf][ks][1], wh[mf][ks][2], wh[mf][ks][3], rl0, rl1);
                }
            }
        }

        // write T tile
        #pragma unroll
        for (int mf = 0; mf < 2; mf++) {
            #pragma unroll
            for (int nf = 0; nf < 2; nf++) {
                int row = 32*wid + 16*mf + g4;
                int col = 8*nf + 2*t4;
                if (col < 12) {
                    u.T[row  ][col  ] = dd[mf][nf][0];
                    u.T[row  ][col+1] = dd[mf][nf][1];
                    u.T[row+8][col  ] = dd[mf][nf][2];
                    u.T[row+8][col+1] = dd[mf][nf][3];
                }
            }
        }
        __syncthreads();

        if (vok) {
            const float* Tr = u.T[tid];
            size_t vp = (size_t)b*N3 + (size_t)vg*3;
            float px = g_vposed[vp], py = g_vposed[vp+1], pz = g_vposed[vp+2];
            float ox = Tr[0]*px + Tr[1]*py + Tr[2]*pz  + Tr[3];
            float oy = Tr[4]*px + Tr[5]*py + Tr[6]*pz  + Tr[7];
            float oz = Tr[8]*px + Tr[9]*py + Tr[10]*pz + Tr[11];
            size_t ob = ((size_t)b*NV + vg)*3;
            out_v[ob]   = ox;
            out_v[ob+1] = oy;
            out_v[ob+2] = oz;
        }
    }
}

// ---------------------------------------------------------------------------
extern "C" void kernel_launch(void* const* d_in, const int* in_sizes, int n_in,
                              void* d_out, int out_size) {
    const float* betas = (const float*)d_in[0];
    const float* grot  = (const float*)d_in[1];
    const float* bpose = (const float*)d_in[2];
    const float* vt    = (const float*)d_in[3];
    const float* sd    = (const float*)d_in[4];
    const float* pd    = (const float*)d_in[5];
    const float* JR    = (const float*)d_in[6];
    const float* w     = (const float*)d_in[7];
    float* out = (float*)d_out;
    float* out_vertices = out;
    float* out_joints = out + (size_t)BATCH*NV*3;

    long nB = (long)(KPOSE + NSHAPE + 2) * N3;
    k_prep_B<<<(unsigned)((nB + 255)/256), 256>>>(pd, sd, vt);
    k_prep_W<<<(NJ*NV + 255)/256, 256>>>(w);
    k_jreg<<<NJ*3, 256>>>(JR, sd, vt);
    k_joints<<<BATCH, 32>>>(betas, grot, bpose, out_joints);
    k_gemm<<<dim3((N3 + GN - 1)/GN, BATCH/GM), 256>>>();
    k_lbs<<<dim3((NV + LVT - 1)/LVT, BATCH/LGB), 256>>>(out_vertices);
}

// round 6
// speedup vs baseline: 1.8642x; 1.2559x over previous
#include <cuda_runtime.h>
#include <cuda_bf16.h>
#include <cstdint>

#define BATCH 1024
#define NV 6890
#define NJ 24
#define NSHAPE 10
#define KPOSE 207
#define N3 (NV*3)          // 20670
#define KA 224             // fp32 A row stride
#define KUSED 218          // valid K rows (207 pf + 10 betas + 1 one)
#define NCHUNK 14          // 224 / 16
#define CHUNK_ELEMS 2048   // 128 x 16 bf16
#define NTILES 162         // ceil(20670/128)
#define MTILES 8           // 1024/128

// LBS kernel tiling
#define LVT 256
#define LGB 16
#define WSTR 260
#define TSTR 13

__constant__ int c_parents[NJ] = {-1,0,0,0,1,2,3,4,5,6,7,8,9,9,9,12,13,14,16,17,18,19,20,21};

// scratch (device globals; zero-initialized; pad chunks never written)
__device__ float g_JRs[NJ*3*NSHAPE];
__device__ float g_Jbase[NJ*3];
__device__ float g_Af[BATCH*KA];
__device__ float g_Arel[BATCH*NJ*12];
__device__ float g_WThi[NJ*NV];
__device__ float g_WTlo[NJ*NV];
__device__ float g_vposed[BATCH*N3];             // 84.7 MB scratch
// 8x8-tile-contiguous bf16 operand chunks (128 rows x 16 k per chunk)
__device__ __nv_bfloat16 g_Asw_h[MTILES*NCHUNK*CHUNK_ELEMS];
__device__ __nv_bfloat16 g_Asw_l[MTILES*NCHUNK*CHUNK_ELEMS];
__device__ __nv_bfloat16 g_Bsw_h[NTILES*NCHUNK*CHUNK_ELEMS];
__device__ __nv_bfloat16 g_Bsw_l[NTILES*NCHUNK*CHUNK_ELEMS];

__device__ __forceinline__ float tf32_rna(float x) {
    unsigned u;
    asm("cvt.rna.tf32.f32 %0, %1;" : "=r"(u) : "f"(x));
    return __uint_as_float(u);
}

__device__ __forceinline__ uint32_t smem_u32(const void* p) {
    uint32_t a;
    asm("{ .reg .u64 t; cvta.to.shared.u64 t, %1; cvt.u32.u64 %0, t; }" : "=r"(a) : "l"(p));
    return a;
}

// tile-contiguous element index within a 128x16 chunk: (r, kk) ->
// tile (r>>3, kk>>3), elem = tile*64 + (r&7)*8 + (kk&7)
__device__ __forceinline__ int tile_idx(int r, int kk) {
    return ((r >> 3)*2 + (kk >> 3))*64 + (r & 7)*8 + (kk & 7);
}

#define CP16(dst, src) \
    asm volatile("cp.async.cg.shared.global [%0], [%1], 16;" :: "r"(dst), "l"(src) : "memory")

#define LDSM4(r, addr) \
    asm volatile("ldmatrix.sync.aligned.m8n8.x4.shared.b16 {%0,%1,%2,%3}, [%4];" \
                 : "=r"((r)[0]), "=r"((r)[1]), "=r"((r)[2]), "=r"((r)[3]) : "r"(addr))

#define MMA_BF16(D, A, B0, B1) \
    asm volatile("mma.sync.aligned.m16n8k16.row.col.f32.bf16.bf16.f32 " \
                 "{%0,%1,%2,%3},{%4,%5,%6,%7},{%8,%9},{%0,%1,%2,%3};" \
                 : "+f"(D[0]), "+f"(D[1]), "+f"(D[2]), "+f"(D[3]) \
                 : "r"((A)[0]), "r"((A)[1]), "r"((A)[2]), "r"((A)[3]), "r"(B0), "r"(B1))

#define MMA_TF32(D, A0,A1,A2,A3, B0,B1) \
    asm volatile("mma.sync.aligned.m16n8k8.row.col.f32.tf32.tf32.f32 " \
                 "{%0,%1,%2,%3},{%4,%5,%6,%7},{%8,%9},{%0,%1,%2,%3};" \
                 : "+f"(D[0]), "+f"(D[1]), "+f"(D[2]), "+f"(D[3]) \
                 : "r"(A0), "r"(A1), "r"(A2), "r"(A3), "r"(B0), "r"(B1))

// ---------------------------------------------------------------------------
// Prep B: bf16 hi/lo tile-contiguous chunks from posedirs/shapedirs/vt.
// ---------------------------------------------------------------------------
__global__ void k_prep_B(const float* __restrict__ pd,
                         const float* __restrict__ sd,
                         const float* __restrict__ vt) {
    long i = (long)blockIdx.x * 256 + threadIdx.x;
    if (i >= (long)KUSED * N3) return;
    int k = (int)(i / N3);
    int n = (int)(i % N3);
    float val;
    if (k < KPOSE) {
        val = pd[(size_t)k*N3 + n];
    } else if (k < KPOSE + NSHAPE) {
        int l = k - KPOSE;
        int v = n / 3, c = n % 3;
        val = sd[v*30 + c*10 + l];
    } else {
        val = vt[n];
    }
    __nv_bfloat16 hi = __float2bfloat16_rn(val);
    __nv_bfloat16 lo = __float2bfloat16_rn(val - __bfloat162float(hi));
    int ntile = n >> 7, c = n & 127;
    size_t base = (size_t)(ntile*NCHUNK + (k >> 4)) * CHUNK_ELEMS
                + tile_idx(c, k & 15);     // B stored n-major (row = n, col = k)
    g_Bsw_h[base] = hi;
    g_Bsw_l[base] = lo;
}

// ---------------------------------------------------------------------------
// Prep A: bf16 hi/lo tile-contiguous chunks from fp32 A rows.
// ---------------------------------------------------------------------------
__global__ void k_prep_A() {
    int i = blockIdx.x * 256 + threadIdx.x;
    if (i >= BATCH * KUSED) return;
    int b = i / KUSED, k = i % KUSED;
    float val = g_Af[b*KA + k];
    __nv_bfloat16 hi = __float2bfloat16_rn(val);
    __nv_bfloat16 lo = __float2bfloat16_rn(val - __bfloat162float(hi));
    int mtile = b >> 7, r = b & 127;
    size_t base = (size_t)(mtile*NCHUNK + (k >> 4)) * CHUNK_ELEMS
                + tile_idx(r, k & 15);
    g_Asw_h[base] = hi;
    g_Asw_l[base] = lo;
}

// ---------------------------------------------------------------------------
// Prep W: lbs_weights transposed, split hi/lo (tf32, for k_lbs).
// ---------------------------------------------------------------------------
__global__ void k_prep_W(const float* __restrict__ w) {
    int i = blockIdx.x * 256 + threadIdx.x;
    if (i >= NJ*NV) return;
    int j = i / NV, v = i % NV;
    float x = w[v*NJ + j];
    float hi = tf32_rna(x);
    g_WThi[i] = hi;
    g_WTlo[i] = tf32_rna(x - hi);
}

// ---------------------------------------------------------------------------
// Fold J_regressor into tiny per-joint tensors.
// ---------------------------------------------------------------------------
__global__ void k_jreg(const float* __restrict__ JR,
                       const float* __restrict__ sd,
                       const float* __restrict__ vt) {
    int j = blockIdx.x / 3;
    int c = blockIdx.x % 3;
    int tid = threadIdx.x;
    float acc[11];
    #pragma unroll
    for (int l = 0; l < 11; l++) acc[l] = 0.f;
    for (int v = tid; v < NV; v += 256) {
        float r = JR[j*NV + v];
        const float* s = &sd[v*30 + c*10];
        #pragma unroll
        for (int l = 0; l < 10; l++) acc[l] += r * s[l];
        acc[10] += r * vt[v*3 + c];
    }
    __shared__ float red[256][12];
    #pragma unroll
    for (int l = 0; l < 11; l++) red[tid][l] = acc[l];
    __syncthreads();
    for (int st = 128; st > 0; st >>= 1) {
        if (tid < st) {
            #pragma unroll
            for (int l = 0; l < 11; l++) red[tid][l] += red[tid + st][l];
        }
        __syncthreads();
    }
    if (tid < 10) g_JRs[(j*3 + c)*NSHAPE + tid] = red[0][tid];
    if (tid == 10) g_Jbase[j*3 + c] = red[0][10];
}

// ---------------------------------------------------------------------------
// Warp per batch: joints, fp32 A row, chain, A_rel.
// ---------------------------------------------------------------------------
__global__ void k_joints(const float* __restrict__ betas,
                         const float* __restrict__ grot,
                         const float* __restrict__ bpose,
                         float* __restrict__ out_joints) {
    int b = blockIdx.x;
    int lane = threadIdx.x;
    __shared__ float sJt[NJ*3];
    __shared__ float sA[NJ*12];

    for (int idx = lane; idx < NJ*3; idx += 32) {
        float v = g_Jbase[idx];
        const float* jr = &g_JRs[idx*NSHAPE];
        const float* be = &betas[b*NSHAPE];
        #pragma unroll
        for (int l = 0; l < NSHAPE; l++) v += jr[l]*be[l];
        sJt[idx] = v;
    }
    for (int idx = lane; idx < KUSED; idx += 32) {
        float val;
        if (idx < KPOSE) {
            int rr = (idx % 9) / 3, cc = idx % 3;
            val = bpose[b*KPOSE + idx] - ((rr == cc) ? 1.f : 0.f);
        } else if (idx < KPOSE + NSHAPE) {
            val = betas[b*NSHAPE + (idx - KPOSE)];
        } else {
            val = 1.f;
        }
        g_Af[b*KA + idx] = val;
    }
    __syncwarp();

    if (lane == 0) {
        const float* R0 = &grot[b*9];
        #pragma unroll
        for (int m = 0; m < 3; m++) {
            sA[m*4+0] = R0[m*3+0];
            sA[m*4+1] = R0[m*3+1];
            sA[m*4+2] = R0[m*3+2];
            sA[m*4+3] = sJt[m];
        }
        for (int j = 1; j < NJ; j++) {
            int p = c_parents[j];
            const float* Rl = &bpose[b*KPOSE + (j-1)*9];
            float tl[3];
            #pragma unroll
            for (int m = 0; m < 3; m++) tl[m] = sJt[j*3+m] - sJt[p*3+m];
            const float* Ap = &sA[p*12];
            float* Aj = &sA[j*12];
            #pragma unroll
            for (int m = 0; m < 3; m++) {
                float r0 = Ap[m*4+0], r1 = Ap[m*4+1], r2 = Ap[m*4+2];
                #pragma unroll
                for (int n = 0; n < 3; n++)
                    Aj[m*4+n] = r0*Rl[0*3+n] + r1*Rl[1*3+n] + r2*Rl[2*3+n];
                Aj[m*4+3] = r0*tl[0] + r1*tl[1] + r2*tl[2] + Ap[m*4+3];
            }
        }
    }
    __syncwarp();

    if (lane < NJ) {
        int j = lane;
        const float* Aj = &sA[j*12];
        float* arel = &g_Arel[(b*NJ + j)*12];
        float jt0 = sJt[j*3+0], jt1 = sJt[j*3+1], jt2 = sJt[j*3+2];
        #pragma unroll
        for (int m = 0; m < 3; m++) {
            float r0 = Aj[m*4+0], r1 = Aj[m*4+1], r2 = Aj[m*4+2];
            float t = Aj[m*4+3];
            out_joints[(b*NJ + j)*3 + m] = t;
            arel[m*4+0] = r0;
            arel[m*4+1] = r1;
            arel[m*4+2] = r2;
            arel[m*4+3] = t - (r0*jt0 + r1*jt1 + r2*jt2);
        }
    }
}

// ---------------------------------------------------------------------------
// GEMM: v_posed(1024 x 20670) = A(1024 x 224) @ B(224 x 20670)
// mma.sync bf16 m16n8k16, 3-pass hi/lo split, ldmatrix fragment loads.
// CTA 128x128, 256 threads / 8 warps (4m x 2n), warp tile 32x64.
// 3-stage 16KB smem ring (Ah|Al|Bh|Bl 4KB each), cp.async, 1 sync/chunk.
// ---------------------------------------------------------------------------
#define STG_BYTES 16384

__global__ __launch_bounds__(256, 2)
void k_gemm() {
    __shared__ __align__(128) char sm[3][STG_BYTES];
    uint32_t sbase = smem_u32(sm);

    int tid = threadIdx.x;
    int lane = tid & 31;
    int wid = tid >> 5;
    int wm = wid & 3;
    int wn = wid >> 2;
    int g4 = lane >> 2;
    int t4 = lane & 3;
    int ntile = blockIdx.x;
    int mtile = blockIdx.y;
    int n0 = ntile * 128;
    int m0 = mtile * 128;

    const char* srcAh = (const char*)&g_Asw_h[(size_t)mtile*NCHUNK*CHUNK_ELEMS];
    const char* srcAl = (const char*)&g_Asw_l[(size_t)mtile*NCHUNK*CHUNK_ELEMS];
    const char* srcBh = (const char*)&g_Bsw_h[(size_t)ntile*NCHUNK*CHUNK_ELEMS];
    const char* srcBl = (const char*)&g_Bsw_l[(size_t)ntile*NCHUNK*CHUNK_ELEMS];

    // per-thread ldmatrix address offsets
    int qa = lane >> 3, ra = lane & 7;
    uint32_t offA[2], offB[4];
    #pragma unroll
    for (int mf = 0; mf < 2; mf++) {
        int tr0 = 4*wm + 2*mf;
        int t = (tr0 + (qa & 1))*2 + (qa >> 1);
        offA[mf] = t*128 + ra*16;
    }
    #pragma unroll
    for (int p = 0; p < 4; p++) {
        int gA = 8*wn + 2*p;
        int t = (gA + (qa >> 1))*2 + (qa & 1);
        offB[p] = t*128 + ra*16;
    }

    auto load_chunk = [&](int s, int ck) {
        uint32_t d = sbase + s*STG_BYTES + tid*16;
        size_t co = (size_t)ck * 4096;
        CP16(d,          srcAh + co + tid*16);
        CP16(d + 4096,   srcAl + co + tid*16);
        CP16(d + 8192,   srcBh + co + tid*16);
        CP16(d + 12288,  srcBl + co + tid*16);
        asm volatile("cp.async.commit_group;" ::: "memory");
    };

    float d[2][8][4];
    #pragma unroll
    for (int mf = 0; mf < 2; mf++)
        #pragma unroll
        for (int f = 0; f < 8; f++)
            #pragma unroll
            for (int q = 0; q < 4; q++) d[mf][f][q] = 0.f;

    load_chunk(0, 0);
    load_chunk(1, 1);

    for (int ck = 0; ck < NCHUNK; ck++) {
        int s = ck % 3;
        if (ck < NCHUNK-1) asm volatile("cp.async.wait_group 1;" ::: "memory");
        else               asm volatile("cp.async.wait_group 0;" ::: "memory");
        __syncthreads();
        if (ck + 2 < NCHUNK) load_chunk((ck + 2) % 3, ck + 2);

        uint32_t sb = sbase + s*STG_BYTES;
        unsigned ah[2][4], al[2][4];
        #pragma unroll
        for (int mf = 0; mf < 2; mf++) {
            LDSM4(ah[mf], sb + offA[mf]);
            LDSM4(al[mf], sb + 4096 + offA[mf]);
        }
        #pragma unroll
        for (int p = 0; p < 4; p++) {
            unsigned bh[4], bl[4];
            LDSM4(bh, sb + 8192  + offB[p]);
            LDSM4(bl, sb + 12288 + offB[p]);
            #pragma unroll
            for (int mf = 0; mf < 2; mf++) {
                MMA_BF16(d[mf][2*p],   ah[mf], bh[0], bh[1]);
                MMA_BF16(d[mf][2*p],   al[mf], bh[0], bh[1]);
                MMA_BF16(d[mf][2*p],   ah[mf], bl[0], bl[1]);
                MMA_BF16(d[mf][2*p+1], ah[mf], bh[2], bh[3]);
                MMA_BF16(d[mf][2*p+1], al[mf], bh[2], bh[3]);
                MMA_BF16(d[mf][2*p+1], ah[mf], bl[2], bl[3]);
            }
        }
    }

    // direct store (float2 pairs, even columns)
    #pragma unroll
    for (int mf = 0; mf < 2; mf++) {
        #pragma unroll
        for (int f = 0; f < 8; f++) {
            int row = m0 + 32*wm + 16*mf + g4;
            int cg = n0 + 64*wn + 8*f + 2*t4;
            if (cg < N3) {
                *(float2*)&g_vposed[(size_t)row*N3 + cg] =
                    make_float2(d[mf][f][0], d[mf][f][1]);
                *(float2*)&g_vposed[(size_t)(row+8)*N3 + cg] =
                    make_float2(d[mf][f][2], d[mf][f][3]);
            }
        }
    }
}

// ---------------------------------------------------------------------------
// LBS: per block 256 vertices x 16 batches (tf32 mma.sync, as R4).
// ---------------------------------------------------------------------------
union ULbs {
    float Wst[NJ][WSTR];
    float T[LVT][TSTR];
};

__global__ __launch_bounds__(256, 2)
void k_lbs(float* __restrict__ out_v) {
    __shared__ ULbs u;
    __shared__ float sRh[NJ][16];
    __shared__ float sRl[NJ][16];

    int tid = threadIdx.x;
    int lane = tid & 31;
    int wid = tid >> 5;
    int g4 = lane >> 2;
    int t4 = lane & 3;
    int v0 = blockIdx.x * LVT;
    int b0 = blockIdx.y * LGB;
    int vg = v0 + tid;
    bool vok = vg < NV;

    unsigned wh[2][3][4], wl[2][3][4];
    #pragma unroll
    for (int k = 0; k < NJ; k++)
        u.Wst[k][tid] = vok ? g_WThi[k*NV + vg] : 0.f;
    __syncthreads();
    #pragma unroll
    for (int mf = 0; mf < 2; mf++) {
        int ar = 32*wid + 16*mf + g4;
        #pragma unroll
        for (int ks = 0; ks < 3; ks++) {
            wh[mf][ks][0] = __float_as_uint(u.Wst[8*ks+t4  ][ar]);
            wh[mf][ks][1] = __float_as_uint(u.Wst[8*ks+t4  ][ar+8]);
            wh[mf][ks][2] = __float_as_uint(u.Wst[8*ks+t4+4][ar]);
            wh[mf][ks][3] = __float_as_uint(u.Wst[8*ks+t4+4][ar+8]);
        }
    }
    __syncthreads();
    #pragma unroll
    for (int k = 0; k < NJ; k++)
        u.Wst[k][tid] = vok ? g_WTlo[k*NV + vg] : 0.f;
    __syncthreads();
    #pragma unroll
    for (int mf = 0; mf < 2; mf++) {
        int ar = 32*wid + 16*mf + g4;
        #pragma unroll
        for (int ks = 0; ks < 3; ks++) {
            wl[mf][ks][0] = __float_as_uint(u.Wst[8*ks+t4  ][ar]);
            wl[mf][ks][1] = __float_as_uint(u.Wst[8*ks+t4  ][ar+8]);
            wl[mf][ks][2] = __float_as_uint(u.Wst[8*ks+t4+4][ar]);
            wl[mf][ks][3] = __float_as_uint(u.Wst[8*ks+t4+4][ar+8]);
        }
    }
    if (tid < NJ*4) {
        int j = tid >> 2, c = 12 + (tid & 3);
        sRh[j][c] = 0.f;
        sRl[j][c] = 0.f;
    }

    for (int bi = 0; bi < LGB; bi++) {
        int b = b0 + bi;
        {
            int i = tid;
            if (i < NJ*12) {
                int j = i / 12, r = i % 12;
                float x = g_Arel[((size_t)b*NJ + j)*12 + r];
                float hi = tf32_rna(x);
                sRh[j][r] = hi;
                sRl[j][r] = tf32_rna(x - hi);
            }
            i = tid + 256;
            if (i < NJ*12) {
                int j = i / 12, r = i % 12;
                float x = g_Arel[((size_t)b*NJ + j)*12 + r];
                float hi = tf32_rna(x);
                sRh[j][r] = hi;
                sRl[j][r] = tf32_rna(x - hi);
            }
        }
        __syncthreads();

        float dd[2][2][4];
        #pragma unroll
        for (int mf = 0; mf < 2; mf++)
            #pragma unroll
            for (int nf = 0; nf < 2; nf++)
                #pragma unroll
                for (int q = 0; q < 4; q++) dd[mf][nf][q] = 0.f;

        #pragma unroll
        for (int ks = 0; ks < 3; ks++) {
            #pragma unroll
            for (int nf = 0; nf < 2; nf++) {
                int rc = 8*nf + g4;
                unsigned rh0 = __float_as_uint(sRh[8*ks+t4  ][rc]);
                unsigned rh1 = __float_as_uint(sRh[8*ks+t4+4][rc]);
                unsigned rl0 = __float_as_uint(sRl[8*ks+t4  ][rc]);
                unsigned rl1 = __float_as_uint(sRl[8*ks+t4+4][rc]);
                #pragma unroll
                for (int mf = 0; mf < 2; mf++) {
                    MMA_TF32(dd[mf][nf], wh[mf][ks][0], wh[mf][ks][1], wh[mf][ks][2], wh[mf][ks][3], rh0, rh1);
                    MMA_TF32(dd[mf][nf], wl[mf][ks][0], wl[mf][ks][1], wl[mf][ks][2], wl[mf][ks][3], rh0, rh1);
                    MMA_TF32(dd[mf][nf], wh[mf][ks][0], wh[mf][ks][1], wh[mf][ks][2], wh[mf][ks][3], rl0, rl1);
                }
            }
        }

        #pragma unroll
        for (int mf = 0; mf < 2; mf++) {
            #pragma unroll
            for (int nf = 0; nf < 2; nf++) {
                int row = 32*wid + 16*mf + g4;
                int col = 8*nf + 2*t4;
                if (col < 12) {
                    u.T[row  ][col  ] = dd[mf][nf][0];
                    u.T[row  ][col+1] = dd[mf][nf][1];
                    u.T[row+8][col  ] = dd[mf][nf][2];
                    u.T[row+8][col+1] = dd[mf][nf][3];
                }
            }
        }
        __syncthreads();

        if (vok) {
            const float* Tr = u.T[tid];
            size_t vp = (size_t)b*N3 + (size_t)vg*3;
            float px = g_vposed[vp], py = g_vposed[vp+1], pz = g_vposed[vp+2];
            float ox = Tr[0]*px + Tr[1]*py + Tr[2]*pz  + Tr[3];
            float oy = Tr[4]*px + Tr[5]*py + Tr[6]*pz  + Tr[7];
            float oz = Tr[8]*px + Tr[9]*py + Tr[10]*pz + Tr[11];
            size_t ob = ((size_t)b*NV + vg)*3;
            out_v[ob]   = ox;
            out_v[ob+1] = oy;
            out_v[ob+2] = oz;
        }
    }
}

// ---------------------------------------------------------------------------
extern "C" void kernel_launch(void* const* d_in, const int* in_sizes, int n_in,
                              void* d_out, int out_size) {
    const float* betas = (const float*)d_in[0];
    const float* grot  = (const float*)d_in[1];
    const float* bpose = (const float*)d_in[2];
    const float* vt    = (const float*)d_in[3];
    const float* sd    = (const float*)d_in[4];
    const float* pd    = (const float*)d_in[5];
    const float* JR    = (const float*)d_in[6];
    const float* w     = (const float*)d_in[7];
    float* out = (float*)d_out;
    float* out_vertices = out;
    float* out_joints = out + (size_t)BATCH*NV*3;

    long nB = (long)KUSED * N3;
    k_prep_B<<<(unsigned)((nB + 255)/256), 256>>>(pd, sd, vt);
    k_prep_W<<<(NJ*NV + 255)/256, 256>>>(w);
    k_jreg<<<NJ*3, 256>>>(JR, sd, vt);
    k_joints<<<BATCH, 32>>>(betas, grot, bpose, out_joints);
    k_prep_A<<<(BATCH*KUSED + 255)/256, 256>>>();
    k_gemm<<<dim3(NTILES, MTILES), 256>>>();
    k_lbs<<<dim3((NV + LVT - 1)/LVT, BATCH/LGB), 256>>>(out_vertices);
}

// round 7
// speedup vs baseline: 2.0275x; 1.0876x over previous
#include <cuda_runtime.h>
#include <cuda_bf16.h>
#include <cstdint>

#define BATCH 1024
#define NV 6890
#define NJ 24
#define NSHAPE 10
#define KPOSE 207
#define N3 (NV*3)          // 20670
#define KA 224             // fp32 A row stride
#define KUSED 218          // valid K rows (207 pf + 10 betas + 1 one)
#define NCHUNK 14          // 224 / 16
#define CHUNK_ELEMS 2048   // 128 x 16 bf16
#define NTILES 162         // ceil(20670/128)
#define MTILES 8           // 1024/128

// LBS kernel tiling
#define LVB 128            // vertices per block
#define LBB 32             // batches per block
#define NSLICE 8           // slices of 4 batches
#define TST 52             // T row stride (floats), 16B-aligned rows

__constant__ int c_parents[NJ] = {-1,0,0,0,1,2,3,4,5,6,7,8,9,9,9,12,13,14,16,17,18,19,20,21};

// scratch (device globals; zero-initialized; pad chunks never written)
__device__ float g_JRs[NJ*3*NSHAPE];
__device__ float g_Jbase[NJ*3];
__device__ float g_Af[BATCH*KA];
__device__ float g_Arel[BATCH*NJ*12];
__device__ __nv_bfloat16 g_Wbh[NJ*NV];           // lbs_weights^T bf16 hi
__device__ __nv_bfloat16 g_Wbl[NJ*NV];           // lbs_weights^T bf16 lo
__device__ float g_vposed[BATCH*N3];             // 84.7 MB scratch
// 8x8-tile-contiguous bf16 operand chunks (128 rows x 16 k per chunk)
__device__ __nv_bfloat16 g_Asw_h[MTILES*NCHUNK*CHUNK_ELEMS];
__device__ __nv_bfloat16 g_Asw_l[MTILES*NCHUNK*CHUNK_ELEMS];
__device__ __nv_bfloat16 g_Bsw_h[NTILES*NCHUNK*CHUNK_ELEMS];
__device__ __nv_bfloat16 g_Bsw_l[NTILES*NCHUNK*CHUNK_ELEMS];

__device__ __forceinline__ uint32_t smem_u32(const void* p) {
    uint32_t a;
    asm("{ .reg .u64 t; cvta.to.shared.u64 t, %1; cvt.u32.u64 %0, t; }" : "=r"(a) : "l"(p));
    return a;
}

// tile-contiguous element index within a 128x16 chunk (2 k-tiles per row-tile)
__device__ __forceinline__ int tile_idx(int r, int kk) {
    return ((r >> 3)*2 + (kk >> 3))*64 + (r & 7)*8 + (kk & 7);
}
// variant for 32-wide k (4 k-tiles per row-tile)
__device__ __forceinline__ int tile_idx4(int r, int kk) {
    return ((r >> 3)*4 + (kk >> 3))*64 + (r & 7)*8 + (kk & 7);
}

#define CP16(dst, src) \
    asm volatile("cp.async.cg.shared.global [%0], [%1], 16;" :: "r"(dst), "l"(src) : "memory")

#define LDSM4(r, addr) \
    asm volatile("ldmatrix.sync.aligned.m8n8.x4.shared.b16 {%0,%1,%2,%3}, [%4];" \
                 : "=r"((r)[0]), "=r"((r)[1]), "=r"((r)[2]), "=r"((r)[3]) : "r"(addr))

#define MMA_BF16(D, A, B0, B1) \
    asm volatile("mma.sync.aligned.m16n8k16.row.col.f32.bf16.bf16.f32 " \
                 "{%0,%1,%2,%3},{%4,%5,%6,%7},{%8,%9},{%0,%1,%2,%3};" \
                 : "+f"(D[0]), "+f"(D[1]), "+f"(D[2]), "+f"(D[3]) \
                 : "r"((A)[0]), "r"((A)[1]), "r"((A)[2]), "r"((A)[3]), "r"(B0), "r"(B1))

// ---------------------------------------------------------------------------
// Prep B: bf16 hi/lo tile-contiguous chunks from posedirs/shapedirs/vt.
// ---------------------------------------------------------------------------
__global__ void k_prep_B(const float* __restrict__ pd,
                         const float* __restrict__ sd,
                         const float* __restrict__ vt) {
    long i = (long)blockIdx.x * 256 + threadIdx.x;
    if (i >= (long)KUSED * N3) return;
    int k = (int)(i / N3);
    int n = (int)(i % N3);
    float val;
    if (k < KPOSE) {
        val = pd[(size_t)k*N3 + n];
    } else if (k < KPOSE + NSHAPE) {
        int l = k - KPOSE;
        int v = n / 3, c = n % 3;
        val = sd[v*30 + c*10 + l];
    } else {
        val = vt[n];
    }
    __nv_bfloat16 hi = __float2bfloat16_rn(val);
    __nv_bfloat16 lo = __float2bfloat16_rn(val - __bfloat162float(hi));
    int ntile = n >> 7, c = n & 127;
    size_t base = (size_t)(ntile*NCHUNK + (k >> 4)) * CHUNK_ELEMS
                + tile_idx(c, k & 15);
    g_Bsw_h[base] = hi;
    g_Bsw_l[base] = lo;
}

// ---------------------------------------------------------------------------
// Prep A: bf16 hi/lo tile-contiguous chunks from fp32 A rows.
// ---------------------------------------------------------------------------
__global__ void k_prep_A() {
    int i = blockIdx.x * 256 + threadIdx.x;
    if (i >= BATCH * KUSED) return;
    int b = i / KUSED, k = i % KUSED;
    float val = g_Af[b*KA + k];
    __nv_bfloat16 hi = __float2bfloat16_rn(val);
    __nv_bfloat16 lo = __float2bfloat16_rn(val - __bfloat162float(hi));
    int mtile = b >> 7, r = b & 127;
    size_t base = (size_t)(mtile*NCHUNK + (k >> 4)) * CHUNK_ELEMS
                + tile_idx(r, k & 15);
    g_Asw_h[base] = hi;
    g_Asw_l[base] = lo;
}

// ---------------------------------------------------------------------------
// Prep W: lbs_weights transposed, bf16 hi/lo.
// ---------------------------------------------------------------------------
__global__ void k_prep_W(const float* __restrict__ w) {
    int i = blockIdx.x * 256 + threadIdx.x;
    if (i >= NJ*NV) return;
    int j = i / NV, v = i % NV;
    float x = w[v*NJ + j];
    __nv_bfloat16 hi = __float2bfloat16_rn(x);
    __nv_bfloat16 lo = __float2bfloat16_rn(x - __bfloat162float(hi));
    g_Wbh[i] = hi;
    g_Wbl[i] = lo;
}

// ---------------------------------------------------------------------------
// Fold J_regressor into tiny per-joint tensors.
// ---------------------------------------------------------------------------
__global__ void k_jreg(const float* __restrict__ JR,
                       const float* __restrict__ sd,
                       const float* __restrict__ vt) {
    int j = blockIdx.x / 3;
    int c = blockIdx.x % 3;
    int tid = threadIdx.x;
    float acc[11];
    #pragma unroll
    for (int l = 0; l < 11; l++) acc[l] = 0.f;
    for (int v = tid; v < NV; v += 256) {
        float r = JR[j*NV + v];
        const float* s = &sd[v*30 + c*10];
        #pragma unroll
        for (int l = 0; l < 10; l++) acc[l] += r * s[l];
        acc[10] += r * vt[v*3 + c];
    }
    __shared__ float red[256][12];
    #pragma unroll
    for (int l = 0; l < 11; l++) red[tid][l] = acc[l];
    __syncthreads();
    for (int st = 128; st > 0; st >>= 1) {
        if (tid < st) {
            #pragma unroll
            for (int l = 0; l < 11; l++) red[tid][l] += red[tid + st][l];
        }
        __syncthreads();
    }
    if (tid < 10) g_JRs[(j*3 + c)*NSHAPE + tid] = red[0][tid];
    if (tid == 10) g_Jbase[j*3 + c] = red[0][10];
}

// ---------------------------------------------------------------------------
// Warp per batch: joints, fp32 A row, chain, A_rel.
// ---------------------------------------------------------------------------
__global__ void k_joints(const float* __restrict__ betas,
                         const float* __restrict__ grot,
                         const float* __restrict__ bpose,
                         float* __restrict__ out_joints) {
    int b = blockIdx.x;
    int lane = threadIdx.x;
    __shared__ float sJt[NJ*3];
    __shared__ float sA[NJ*12];

    for (int idx = lane; idx < NJ*3; idx += 32) {
        float v = g_Jbase[idx];
        const float* jr = &g_JRs[idx*NSHAPE];
        const float* be = &betas[b*NSHAPE];
        #pragma unroll
        for (int l = 0; l < NSHAPE; l++) v += jr[l]*be[l];
        sJt[idx] = v;
    }
    for (int idx = lane; idx < KUSED; idx += 32) {
        float val;
        if (idx < KPOSE) {
            int rr = (idx % 9) / 3, cc = idx % 3;
            val = bpose[b*KPOSE + idx] - ((rr == cc) ? 1.f : 0.f);
        } else if (idx < KPOSE + NSHAPE) {
            val = betas[b*NSHAPE + (idx - KPOSE)];
        } else {
            val = 1.f;
        }
        g_Af[b*KA + idx] = val;
    }
    __syncwarp();

    if (lane == 0) {
        const float* R0 = &grot[b*9];
        #pragma unroll
        for (int m = 0; m < 3; m++) {
            sA[m*4+0] = R0[m*3+0];
            sA[m*4+1] = R0[m*3+1];
            sA[m*4+2] = R0[m*3+2];
            sA[m*4+3] = sJt[m];
        }
        for (int j = 1; j < NJ; j++) {
            int p = c_parents[j];
            const float* Rl = &bpose[b*KPOSE + (j-1)*9];
            float tl[3];
            #pragma unroll
            for (int m = 0; m < 3; m++) tl[m] = sJt[j*3+m] - sJt[p*3+m];
            const float* Ap = &sA[p*12];
            float* Aj = &sA[j*12];
            #pragma unroll
            for (int m = 0; m < 3; m++) {
                float r0 = Ap[m*4+0], r1 = Ap[m*4+1], r2 = Ap[m*4+2];
                #pragma unroll
                for (int n = 0; n < 3; n++)
                    Aj[m*4+n] = r0*Rl[0*3+n] + r1*Rl[1*3+n] + r2*Rl[2*3+n];
                Aj[m*4+3] = r0*tl[0] + r1*tl[1] + r2*tl[2] + Ap[m*4+3];
            }
        }
    }
    __syncwarp();

    if (lane < NJ) {
        int j = lane;
        const float* Aj = &sA[j*12];
        float* arel = &g_Arel[(b*NJ + j)*12];
        float jt0 = sJt[j*3+0], jt1 = sJt[j*3+1], jt2 = sJt[j*3+2];
        #pragma unroll
        for (int m = 0; m < 3; m++) {
            float r0 = Aj[m*4+0], r1 = Aj[m*4+1], r2 = Aj[m*4+2];
            float t = Aj[m*4+3];
            out_joints[(b*NJ + j)*3 + m] = t;
            arel[m*4+0] = r0;
            arel[m*4+1] = r1;
            arel[m*4+2] = r2;
            arel[m*4+3] = t - (r0*jt0 + r1*jt1 + r2*jt2);
        }
    }
}

// ---------------------------------------------------------------------------
// GEMM: v_posed = A(1024x224) @ B(224x20670), bf16 3-pass, ldmatrix (as R6).
// ---------------------------------------------------------------------------
#define STG_BYTES 16384

__global__ __launch_bounds__(256, 2)
void k_gemm() {
    __shared__ __align__(128) char sm[3][STG_BYTES];
    uint32_t sbase = smem_u32(sm);

    int tid = threadIdx.x;
    int lane = tid & 31;
    int wid = tid >> 5;
    int wm = wid & 3;
    int wn = wid >> 2;
    int g4 = lane >> 2;
    int t4 = lane & 3;
    int ntile = blockIdx.x;
    int mtile = blockIdx.y;
    int n0 = ntile * 128;
    int m0 = mtile * 128;

    const char* srcAh = (const char*)&g_Asw_h[(size_t)mtile*NCHUNK*CHUNK_ELEMS];
    const char* srcAl = (const char*)&g_Asw_l[(size_t)mtile*NCHUNK*CHUNK_ELEMS];
    const char* srcBh = (const char*)&g_Bsw_h[(size_t)ntile*NCHUNK*CHUNK_ELEMS];
    const char* srcBl = (const char*)&g_Bsw_l[(size_t)ntile*NCHUNK*CHUNK_ELEMS];

    int qa = lane >> 3, ra = lane & 7;
    uint32_t offA[2], offB[4];
    #pragma unroll
    for (int mf = 0; mf < 2; mf++) {
        int tr0 = 4*wm + 2*mf;
        int t = (tr0 + (qa & 1))*2 + (qa >> 1);
        offA[mf] = t*128 + ra*16;
    }
    #pragma unroll
    for (int p = 0; p < 4; p++) {
        int gA = 8*wn + 2*p;
        int t = (gA + (qa >> 1))*2 + (qa & 1);
        offB[p] = t*128 + ra*16;
    }

    auto load_chunk = [&](int s, int ck) {
        uint32_t d = sbase + s*STG_BYTES + tid*16;
        size_t co = (size_t)ck * 4096;
        CP16(d,          srcAh + co + tid*16);
        CP16(d + 4096,   srcAl + co + tid*16);
        CP16(d + 8192,   srcBh + co + tid*16);
        CP16(d + 12288,  srcBl + co + tid*16);
        asm volatile("cp.async.commit_group;" ::: "memory");
    };

    float d[2][8][4];
    #pragma unroll
    for (int mf = 0; mf < 2; mf++)
        #pragma unroll
        for (int f = 0; f < 8; f++)
            #pragma unroll
            for (int q = 0; q < 4; q++) d[mf][f][q] = 0.f;

    load_chunk(0, 0);
    load_chunk(1, 1);

    for (int ck = 0; ck < NCHUNK; ck++) {
        int s = ck % 3;
        if (ck < NCHUNK-1) asm volatile("cp.async.wait_group 1;" ::: "memory");
        else               asm volatile("cp.async.wait_group 0;" ::: "memory");
        __syncthreads();
        if (ck + 2 < NCHUNK) load_chunk((ck + 2) % 3, ck + 2);

        uint32_t sb = sbase + s*STG_BYTES;
        unsigned ah[2][4], al[2][4];
        #pragma unroll
        for (int mf = 0; mf < 2; mf++) {
            LDSM4(ah[mf], sb + offA[mf]);
            LDSM4(al[mf], sb + 4096 + offA[mf]);
        }
        #pragma unroll
        for (int p = 0; p < 4; p++) {
            unsigned bh[4], bl[4];
            LDSM4(bh, sb + 8192  + offB[p]);
            LDSM4(bl, sb + 12288 + offB[p]);
            #pragma unroll
            for (int mf = 0; mf < 2; mf++) {
                MMA_BF16(d[mf][2*p],   ah[mf], bh[0], bh[1]);
                MMA_BF16(d[mf][2*p],   al[mf], bh[0], bh[1]);
                MMA_BF16(d[mf][2*p],   ah[mf], bl[0], bl[1]);
                MMA_BF16(d[mf][2*p+1], ah[mf], bh[2], bh[3]);
                MMA_BF16(d[mf][2*p+1], al[mf], bh[2], bh[3]);
                MMA_BF16(d[mf][2*p+1], ah[mf], bl[2], bl[3]);
            }
        }
    }

    #pragma unroll
    for (int mf = 0; mf < 2; mf++) {
        #pragma unroll
        for (int f = 0; f < 8; f++) {
            int row = m0 + 32*wm + 16*mf + g4;
            int cg = n0 + 64*wn + 8*f + 2*t4;
            if (cg < N3) {
                *(float2*)&g_vposed[(size_t)row*N3 + cg] =
                    make_float2(d[mf][f][0], d[mf][f][1]);
                *(float2*)&g_vposed[(size_t)(row+8)*N3 + cg] =
                    make_float2(d[mf][f][2], d[mf][f][3]);
            }
        }
    }
}

// ---------------------------------------------------------------------------
// LBS: block = 128 vertices x 32 batches (8 slices of 4).
// T(128 x 48) = W(128x32) @ [Arel_b0|..|Arel_b3](32x48), bf16 3-pass MMA.
// W fragments in registers across all slices; then out = T_R @ p + T_t.
// ---------------------------------------------------------------------------
union ULbs {
    __nv_bfloat16 Wst[2][LVB*32];   // [hi/lo] tile-contiguous (4 k-tiles/row-tile)
    float T[LVB*TST];
};

__global__ __launch_bounds__(256, 4)
void k_lbs(float* __restrict__ out_v) {
    __shared__ ULbs u;
    __shared__ __nv_bfloat16 sRh[48*32];   // Arel slice, n-major tile-contiguous
    __shared__ __nv_bfloat16 sRl[48*32];

    int tid = threadIdx.x;
    int lane = tid & 31;
    int wid = tid >> 5;
    int g4 = lane >> 2;
    int t4 = lane & 3;
    int qa = lane >> 3, ra = lane & 7;
    int v0 = blockIdx.x * LVB;
    int b0 = blockIdx.y * LBB;

    // stage W (verts x 32k, zeros for k>=24 and pad verts)
    const __nv_bfloat16 zero = __float2bfloat16_rn(0.f);
    for (int i = tid; i < LVB*32; i += 256) {
        int v = i >> 5, k = i & 31;
        int vg = v0 + v;
        __nv_bfloat16 h = zero, l = zero;
        if (k < NJ && vg < NV) {
            h = g_Wbh[k*NV + vg];
            l = g_Wbl[k*NV + vg];
        }
        int ti = tile_idx4(v, k);
        u.Wst[0][ti] = h;
        u.Wst[1][ti] = l;
    }
    __syncthreads();

    // extract W fragments (warp owns rows 16*wid..16*wid+15)
    uint32_t wbase = smem_u32(u.Wst[0]);
    unsigned wh[2][4], wl[2][4];
    #pragma unroll
    for (int ks = 0; ks < 2; ks++) {
        int t = (2*wid + (qa & 1))*4 + 2*ks + (qa >> 1);
        LDSM4(wh[ks], wbase + t*128 + ra*16);
        LDSM4(wl[ks], wbase + 8192 + t*128 + ra*16);
    }

    uint32_t rbase_h = smem_u32(sRh);
    uint32_t rbase_l = smem_u32(sRl);
    int vert = tid & 127;
    int half = tid >> 7;
    int vgc = v0 + vert;

    for (int s = 0; s < NSLICE; s++) {
        __syncthreads();   // prev consume done (T safe) + W extraction done (slice 0)

        // stage Arel slice: n = bb*12 + r (48), k = j (32, zeros k>=24)
        for (int i = tid; i < 48*32; i += 256) {
            int n = i >> 5, k = i & 31;
            __nv_bfloat16 h = zero, l = zero;
            if (k < NJ) {
                int bb = n / 12, r = n % 12;
                float x = g_Arel[((size_t)(b0 + s*4 + bb)*NJ + k)*12 + r];
                h = __float2bfloat16_rn(x);
                l = __float2bfloat16_rn(x - __bfloat162float(h));
            }
            int ti = tile_idx4(n, k);
            sRh[ti] = h;
            sRl[ti] = l;
        }
        __syncthreads();

        float d[6][4];
        #pragma unroll
        for (int f = 0; f < 6; f++)
            #pragma unroll
            for (int q = 0; q < 4; q++) d[f][q] = 0.f;

        #pragma unroll
        for (int ks = 0; ks < 2; ks++) {
            #pragma unroll
            for (int p = 0; p < 3; p++) {
                int t = (2*p + (qa >> 1))*4 + 2*ks + (qa & 1);
                unsigned bh[4], bl[4];
                LDSM4(bh, rbase_h + t*128 + ra*16);
                LDSM4(bl, rbase_l + t*128 + ra*16);
                MMA_BF16(d[2*p],   wh[ks], bh[0], bh[1]);
                MMA_BF16(d[2*p],   wl[ks], bh[0], bh[1]);
                MMA_BF16(d[2*p],   wh[ks], bl[0], bl[1]);
                MMA_BF16(d[2*p+1], wh[ks], bh[2], bh[3]);
                MMA_BF16(d[2*p+1], wl[ks], bh[2], bh[3]);
                MMA_BF16(d[2*p+1], wh[ks], bl[2], bl[3]);
            }
        }

        // write T tile
        #pragma unroll
        for (int f = 0; f < 6; f++) {
            int row = 16*wid + g4;
            int col = 8*f + 2*t4;
            u.T[row*TST + col]       = d[f][0];
            u.T[row*TST + col + 1]   = d[f][1];
            u.T[(row+8)*TST + col]   = d[f][2];
            u.T[(row+8)*TST + col+1] = d[f][3];
        }
        __syncthreads();

        // consume: thread handles (vert, 2 batches)
        if (vgc < NV) {
            #pragma unroll
            for (int x = 0; x < 2; x++) {
                int bb = half*2 + x;
                int bglob = b0 + s*4 + bb;
                const float4* Tq = (const float4*)&u.T[vert*TST + bb*12];
                float4 A0 = Tq[0], A1 = Tq[1], A2 = Tq[2];
                size_t vp = (size_t)bglob*N3 + (size_t)vgc*3;
                float px = g_vposed[vp], py = g_vposed[vp+1], pz = g_vposed[vp+2];
                float ox = A0.x*px + A0.y*py + A0.z*pz + A0.w;
                float oy = A1.x*px + A1.y*py + A1.z*pz + A1.w;
                float oz = A2.x*px + A2.y*py + A2.z*pz + A2.w;
                size_t ob = ((size_t)bglob*NV + vgc)*3;
                out_v[ob]   = ox;
                out_v[ob+1] = oy;
                out_v[ob+2] = oz;
            }
        }
    }
}

// ---------------------------------------------------------------------------
extern "C" void kernel_launch(void* const* d_in, const int* in_sizes, int n_in,
                              void* d_out, int out_size) {
    const float* betas = (const float*)d_in[0];
    const float* grot  = (const float*)d_in[1];
    const float* bpose = (const float*)d_in[2];
    const float* vt    = (const float*)d_in[3];
    const float* sd    = (const float*)d_in[4];
    const float* pd    = (const float*)d_in[5];
    const float* JR    = (const float*)d_in[6];
    const float* w     = (const float*)d_in[7];
    float* out = (float*)d_out;
    float* out_vertices = out;
    float* out_joints = out + (size_t)BATCH*NV*3;

    long nB = (long)KUSED * N3;
    k_prep_B<<<(unsigned)((nB + 255)/256), 256>>>(pd, sd, vt);
    k_prep_W<<<(NJ*NV + 255)/256, 256>>>(w);
    k_jreg<<<NJ*3, 256>>>(JR, sd, vt);
    k_joints<<<BATCH, 32>>>(betas, grot, bpose, out_joints);
    k_prep_A<<<(BATCH*KUSED + 255)/256, 256>>>();
    k_gemm<<<dim3(NTILES, MTILES), 256>>>();
    k_lbs<<<dim3((NV + LVB - 1)/LVB, BATCH/LBB), 256>>>(out_vertices);
}